// round 14
// baseline (speedup 1.0000x reference)
#include <cuda_runtime.h>
#include <cstdint>

#define BB 8
#define NN 2048
#define KK 20
#define TPW 4    // rows (warps) per topk block
#define NT (NN / 128)            // 16 tiles per dim
#define NPAIR (NT * (NT + 1) / 2) // 136 upper-tri tile pairs

// ---------------- static scratch (no runtime allocation allowed) ----------------
__device__ float g_xt[BB * 3 * NN];
__device__ float g_xx[BB * NN];
__device__ float g_dist[(size_t)BB * NN * NN];          // 134 MB (also reused as vmax/vmin scratch)
__device__ int   g_idx[BB * NN * KK];
__device__ float g_A[(size_t)BB * 256 * NN];            // [b][o][n] 16 MB
__device__ float g_Cc[(size_t)BB * 256 * NN];           // [b][o][n] 16 MB
__device__ float g_xcat[(size_t)BB * 512 * NN];         // [b][c][n] 33 MB (x1|x2|x3|x4)
__device__ float g_sum[512];
__device__ float g_sumsq[512];
__device__ float g_scale[512];
__device__ float g_shift[512];
__device__ float g_pooled[BB * 512];
__device__ unsigned g_ymax[BB * 512];
__device__ unsigned g_ymin[BB * 512];

// ---------------- transpose x (B,N,3) -> (B,3,N) ----------------
__global__ void xt_kernel(const float* __restrict__ x) {
    int i = blockIdx.x * 256 + threadIdx.x;       // b*NN + n
    if (i >= BB * NN) return;
    int b = i >> 11, n = i & (NN - 1);
    #pragma unroll
    for (int c = 0; c < 3; c++)
        g_xt[(b * 3 + c) * NN + n] = x[(size_t)i * 3 + c];
}

// ---------------- squared norms per point ----------------
__global__ void xx_kernel(const float* __restrict__ Xall, int C, int bstride) {
    int i = blockIdx.x * 256 + threadIdx.x;       // b*NN + n
    int b = i >> 11, n = i & (NN - 1);
    const float* X = Xall + (size_t)b * bstride + n;
    float s = 0.f;
    for (int c = 0; c < C; c++) { float v = X[(size_t)c * NN]; s += v * v; }
    g_xx[i] = s;
}

// ---------------- distance matrix: SYMMETRIC upper-tri tile pairs (R12-exact) ----------------
__global__ __launch_bounds__(256) void knn_dist_kernel(const float* __restrict__ Xall,
                                                       int C, int bstride) {
    int b = blockIdx.z;
    const float* X = Xall + (size_t)b * bstride;
    const float* xxr = g_xx + b * NN;
    float* D = g_dist + (size_t)b * NN * NN;

    // decode upper-tri pair (ti <= tj)
    int pair = blockIdx.x;
    int ti = 0, remp = pair;
    while (remp >= NT - ti) { remp -= NT - ti; ti++; }
    int tj = ti + remp;
    int n0 = ti * 128, m0 = tj * 128;

    __shared__ float Ns[2][8][132];
    __shared__ float Ms[2][8][132];
    __shared__ float Ts[32][132];                  // slab transpose buffer
    int t = threadIdx.x;
    int to = t >> 4, tn = t & 15;
    int lk = (t * 4) >> 7, lc = (t * 4) & 127;     // this thread's load slot
    float acc[8][8] = {};
    int nch = (C + 7) / 8;

    // preload chunk 0
    {
        float4 vn = make_float4(0.f, 0.f, 0.f, 0.f), vm = vn;
        if (lk < C) {
            vn = *reinterpret_cast<const float4*>(&X[(size_t)lk * NN + n0 + lc]);
            vm = *reinterpret_cast<const float4*>(&X[(size_t)lk * NN + m0 + lc]);
        }
        *reinterpret_cast<float4*>(&Ns[0][lk][lc]) = vn;
        *reinterpret_cast<float4*>(&Ms[0][lk][lc]) = vm;
    }
    __syncthreads();

    for (int ch = 0; ch < nch; ch++) {
        int cur = ch & 1;
        float4 pn = make_float4(0.f, 0.f, 0.f, 0.f), pm = pn;
        if (ch + 1 < nch) {
            int kg = (ch + 1) * 8 + lk;
            if (kg < C) {
                pn = *reinterpret_cast<const float4*>(&X[(size_t)kg * NN + n0 + lc]);
                pm = *reinterpret_cast<const float4*>(&X[(size_t)kg * NN + m0 + lc]);
            }
        }
        #pragma unroll
        for (int k = 0; k < 8; k++) {
            float a[8], bb_[8];
            *reinterpret_cast<float4*>(&a[0]) = *reinterpret_cast<const float4*>(&Ns[cur][k][to * 8]);
            *reinterpret_cast<float4*>(&a[4]) = *reinterpret_cast<const float4*>(&Ns[cur][k][to * 8 + 4]);
            *reinterpret_cast<float4*>(&bb_[0]) = *reinterpret_cast<const float4*>(&Ms[cur][k][tn * 8]);
            *reinterpret_cast<float4*>(&bb_[4]) = *reinterpret_cast<const float4*>(&Ms[cur][k][tn * 8 + 4]);
            #pragma unroll
            for (int i = 0; i < 8; i++)
                #pragma unroll
                for (int j = 0; j < 8; j++)
                    acc[i][j] += a[i] * bb_[j];
        }
        __syncthreads();
        if (ch + 1 < nch) {
            *reinterpret_cast<float4*>(&Ns[cur ^ 1][lk][lc]) = pn;
            *reinterpret_cast<float4*>(&Ms[cur ^ 1][lk][lc]) = pm;
            __syncthreads();
        }
    }

    // direct tile write (rows n, cols m)
    #pragma unroll
    for (int i = 0; i < 8; i++) {
        int n = n0 + to * 8 + i;
        float xn = xxr[n];
        #pragma unroll
        for (int jj = 0; jj < 2; jj++) {
            float4 v4;
            float* vp = &v4.x;
            #pragma unroll
            for (int j = 0; j < 4; j++) {
                int m = m0 + tn * 8 + jj * 4 + j;
                float v = 2.0f * acc[i][jj * 4 + j] - xn;  // diag: 2v - v = v exactly
                vp[j] = v - xxr[m];                        // diag: v - v = 0 exactly
            }
            *reinterpret_cast<float4*>(&D[(size_t)n * NN + m0 + tn * 8 + jj * 4]) = v4;
        }
    }

    // mirrored tile write (rows m, cols n) via 32-row slab transpose in smem
    if (ti != tj) {
        #pragma unroll
        for (int p = 0; p < 4; p++) {
            __syncthreads();                       // protect Ts from previous slab reads
            if ((tn >> 2) == p) {
                int lt = tn & 3;
                #pragma unroll
                for (int j = 0; j < 8; j++) {
                    int m = m0 + tn * 8 + j;
                    float xm = xxr[m];
                    #pragma unroll
                    for (int i = 0; i < 8; i++) {
                        int n = n0 + to * 8 + i;
                        float v = 2.0f * acc[i][j] - xm;   // mirror: xx[m] first
                        Ts[lt * 8 + j][to * 8 + i] = v - xxr[n];
                    }
                }
            }
            __syncthreads();
            int lm = t >> 3;                        // 0..31
            int c0 = (t & 7) * 16;
            int mg = m0 + p * 32 + lm;
            float* drow = &D[(size_t)mg * NN + n0 + c0];
            #pragma unroll
            for (int q = 0; q < 4; q++)
                *reinterpret_cast<float4*>(&drow[q * 4]) =
                    *reinterpret_cast<const float4*>(&Ts[lm][c0 + q * 4]);
        }
    }
}

// ---------------- top-K: warp-per-row radix select; ballot-based output slots ---------------
// Selection passes identical (same T/rem). Output pass: ballot+popc prefix replaces
// same-address smem atomics; write order = lane-ascending per r, matching the
// deterministic order observed for same-instruction atomics.
__global__ __launch_bounds__(32 * TPW) void topk_kernel() {
    __shared__ unsigned hist[TPW][256];
    __shared__ int cand[TPW][64];
    int warp = threadIdx.x >> 5, lane = threadIdx.x & 31;
    int row = blockIdx.x * TPW + warp;       // b*NN + n
    const float4* D4 = reinterpret_cast<const float4*>(g_dist + (size_t)row * NN);
    unsigned lmask_lt = (1u << lane) - 1u;

    // keys in registers: key[j*4+q] is element i = j*128 + lane*4 + q
    unsigned key[64];
    #pragma unroll
    for (int j = 0; j < 16; j++) {
        float4 d4 = D4[j * 32 + lane];
        const float* dp = &d4.x;
        #pragma unroll
        for (int q = 0; q < 4; q++) {
            unsigned u = __float_as_uint(dp[q]);
            key[j * 4 + q] = (u & 0x80000000u) ? ~u : (u | 0x80000000u);
        }
    }

    unsigned prefix = 0; int rem = KK;
    #pragma unroll
    for (int pass = 0; pass < 4; pass++) {
        int shift = 24 - 8 * pass;
        #pragma unroll
        for (int j = lane; j < 256; j += 32) hist[warp][j] = 0;
        __syncwarp();
        #pragma unroll
        for (int r = 0; r < 64; r++) {
            unsigned k = key[r];
            if (pass == 0 || (k >> (shift + 8)) == prefix)
                atomicAdd(&hist[warp][(k >> shift) & 0xFF], 1u);
        }
        __syncwarp();
        int base = 255 - lane * 8;
        unsigned h[8]; unsigned s = 0;
        #pragma unroll
        for (int j = 0; j < 8; j++) { h[j] = hist[warp][base - j]; s += h[j]; }
        unsigned pre = s;
        #pragma unroll
        for (int off = 1; off < 32; off <<= 1) {
            unsigned v = __shfl_up_sync(0xffffffffu, pre, off);
            if (lane >= off) pre += v;
        }
        unsigned excl = pre - s;
        bool owner = (excl < (unsigned)rem) && ((unsigned)rem <= excl + s);
        unsigned m = __ballot_sync(0xffffffffu, owner);
        int ol = __ffs(m) - 1;
        unsigned nb = 0; int nrem = 0;
        if (owner) {
            unsigned cum = excl;
            #pragma unroll
            for (int j = 0; j < 8; j++) {
                if (cum + h[j] >= (unsigned)rem) { nb = (unsigned)(base - j); nrem = rem - (int)cum; break; }
                cum += h[j];
            }
        }
        nb = __shfl_sync(0xffffffffu, nb, ol);
        nrem = __shfl_sync(0xffffffffu, nrem, ol);
        prefix = (prefix << 8) | nb;
        rem = nrem;
        __syncwarp();
    }

    unsigned T = prefix;                 // key of the 20th largest
    int* outp = &g_idx[(size_t)row * KK];
    int baseG = 0, baseC = 0;
    #pragma unroll
    for (int r = 0; r < 64; r++) {
        unsigned k = key[r];
        bool g = (k > T), e = (k == T);
        unsigned mg = __ballot_sync(0xffffffffu, g);
        unsigned me = __ballot_sync(0xffffffffu, e);
        int i = (r >> 2) * 128 + lane * 4 + (r & 3);
        if (g) outp[baseG + __popc(mg & lmask_lt)] = i;
        if (e) {
            int c = baseC + __popc(me & lmask_lt);
            if (c < 64) cand[warp][c] = i;
        }
        baseG += __popc(mg);
        baseC += __popc(me);
    }
    __syncwarp();
    if (lane == 0) {
        int base = baseG;
        int cc = baseC;
        if (cc == rem) {
            for (int i = 0; i < rem; i++) outp[base + i] = cand[warp][i];
        } else if (cc <= 64) {
            for (int r = 0; r < rem; r++) {          // ties: lowest indices
                int best = NN, bi = -1;
                for (int i = 0; i < cc; i++)
                    if (cand[warp][i] < best) { best = cand[warp][i]; bi = i; }
                outp[base + r] = best;
                cand[warp][bi] = NN;
            }
        } else {                                     // pathological: many exact ties
            const float* D = g_dist + (size_t)row * NN;
            int got = 0;
            for (int i = 0; i < NN && got < rem; i++) {
                unsigned u = __float_as_uint(D[i]);
                unsigned k = (u & 0x80000000u) ? ~u : (u | 0x80000000u);
                if (k == T) outp[base + got++] = i;
            }
        }
    }
}

// ---------------- edge GEMM: A[o][n] = Wl@X, Cc[o][n] = (Wr-Wl)@X  (R9-exact) ----------------
__global__ __launch_bounds__(256) void edge_gemm_kernel(const float* __restrict__ W,
                                                        const float* __restrict__ Xall,
                                                        int C, int O, int bstride) {
    int b = blockIdx.z;
    const float* X = Xall + (size_t)b * bstride;
    float* Aout = g_A + (size_t)b * O * NN;
    float* Cout = g_Cc + (size_t)b * O * NN;
    int o0 = blockIdx.y * 64, n0 = blockIdx.x * 64;
    __shared__ float Xs[16][68];
    __shared__ float Wl[16][68];
    __shared__ float Wd[16][68];
    int t = threadIdx.x;
    int to = t >> 4, tn = t & 15;
    float accA[4][4] = {}, accC[4][4] = {};
    int C2 = 2 * C;
    for (int kk = 0; kk < C; kk += 16) {
        for (int i = t; i < 16 * 64; i += 256) {
            int k = i & 15, o = i >> 4;
            float wl = 0.f, wr = 0.f;
            if (kk + k < C) {
                wl = W[(size_t)(o0 + o) * C2 + kk + k];
                wr = W[(size_t)(o0 + o) * C2 + C + kk + k];
            }
            Wl[k][o] = wl; Wd[k][o] = wr - wl;
        }
        for (int i = t; i < 16 * 64; i += 256) {
            int k = i >> 6, n = i & 63;
            Xs[k][n] = (kk + k < C) ? X[(size_t)(kk + k) * NN + n0 + n] : 0.f;
        }
        __syncthreads();
        #pragma unroll
        for (int k = 0; k < 16; k++) {
            float4 wo4 = *reinterpret_cast<const float4*>(&Wl[k][to * 4]);
            float4 wd4 = *reinterpret_cast<const float4*>(&Wd[k][to * 4]);
            float4 xv4 = *reinterpret_cast<const float4*>(&Xs[k][tn * 4]);
            const float* wo = &wo4.x;
            const float* wd = &wd4.x;
            const float* xv = &xv4.x;
            #pragma unroll
            for (int i = 0; i < 4; i++)
                #pragma unroll
                for (int j = 0; j < 4; j++) {
                    accA[i][j] += wo[i] * xv[j];
                    accC[i][j] += wd[i] * xv[j];
                }
        }
        __syncthreads();
    }
    #pragma unroll
    for (int i = 0; i < 4; i++) {
        int o = o0 + to * 4 + i;
        float4 a4, c4;
        #pragma unroll
        for (int j = 0; j < 4; j++) { (&a4.x)[j] = accA[i][j]; (&c4.x)[j] = accC[i][j]; }
        *reinterpret_cast<float4*>(&Aout[(size_t)o * NN + n0 + tn * 4]) = a4;
        *reinterpret_cast<float4*>(&Cout[(size_t)o * NN + n0 + tn * 4]) = c4;
    }
}

// ---------------- gemm5: 128x128 tile, 8x8 micro-tile, fused stats epilogue (R13-exact) -----
__global__ __launch_bounds__(256) void gemm5_kernel(const float* __restrict__ W) {
    int b = blockIdx.z;
    const float* X = g_xcat + (size_t)b * 512 * NN;
    int o0 = blockIdx.y * 128, n0 = blockIdx.x * 128;
    __shared__ float Xs[2][8][132];
    __shared__ float Ws[2][8][132];
    int t = threadIdx.x;
    int to = t >> 4, tn = t & 15;
    int lo = t & 127, lhalf = (t >> 7) * 4;
    int lk = (t * 4) >> 7, ln = (t * 4) & 127;
    float acc[8][8] = {};

    // preload chunk 0
    {
        float4 w4 = *reinterpret_cast<const float4*>(&W[(size_t)(o0 + lo) * 512 + lhalf]);
        const float* wp = &w4.x;
        #pragma unroll
        for (int q = 0; q < 4; q++) Ws[0][lhalf + q][lo] = wp[q];
        *reinterpret_cast<float4*>(&Xs[0][lk][ln]) =
            *reinterpret_cast<const float4*>(&X[(size_t)lk * NN + n0 + ln]);
    }
    __syncthreads();

    for (int ch = 0; ch < 64; ch++) {
        int cur = ch & 1;
        float4 pw = make_float4(0.f, 0.f, 0.f, 0.f), px = pw;
        if (ch + 1 < 64) {
            int kk = (ch + 1) * 8;
            pw = *reinterpret_cast<const float4*>(&W[(size_t)(o0 + lo) * 512 + kk + lhalf]);
            px = *reinterpret_cast<const float4*>(&X[(size_t)(kk + lk) * NN + n0 + ln]);
        }
        #pragma unroll
        for (int k = 0; k < 8; k++) {
            float a[8], x_[8];
            *reinterpret_cast<float4*>(&a[0]) = *reinterpret_cast<const float4*>(&Ws[cur][k][to * 8]);
            *reinterpret_cast<float4*>(&a[4]) = *reinterpret_cast<const float4*>(&Ws[cur][k][to * 8 + 4]);
            *reinterpret_cast<float4*>(&x_[0]) = *reinterpret_cast<const float4*>(&Xs[cur][k][tn * 8]);
            *reinterpret_cast<float4*>(&x_[4]) = *reinterpret_cast<const float4*>(&Xs[cur][k][tn * 8 + 4]);
            #pragma unroll
            for (int i = 0; i < 8; i++)
                #pragma unroll
                for (int j = 0; j < 8; j++)
                    acc[i][j] += a[i] * x_[j];
        }
        __syncthreads();
        if (ch + 1 < 64) {
            const float* wp = &pw.x;
            #pragma unroll
            for (int q = 0; q < 4; q++) Ws[cur ^ 1][lhalf + q][lo] = wp[q];
            *reinterpret_cast<float4*>(&Xs[cur ^ 1][lk][ln]) = px;
            __syncthreads();
        }
    }

    // epilogue: per-o-row stats over this tile's 128 n-cols (16-lane shuffle reduce)
    int b512 = b * 512;
    #pragma unroll
    for (int i = 0; i < 8; i++) {
        int o = o0 + to * 8 + i;
        float s = 0.f, s2 = 0.f, mx = -3.4e38f, mn = 3.4e38f;
        #pragma unroll
        for (int j = 0; j < 8; j++) {
            float v = acc[i][j];
            s += v; s2 += v * v;
            mx = fmaxf(mx, v); mn = fminf(mn, v);
        }
        #pragma unroll
        for (int off = 8; off > 0; off >>= 1) {
            s  += __shfl_down_sync(0xffffffffu, s, off, 16);
            s2 += __shfl_down_sync(0xffffffffu, s2, off, 16);
            mx = fmaxf(mx, __shfl_down_sync(0xffffffffu, mx, off, 16));
            mn = fminf(mn, __shfl_down_sync(0xffffffffu, mn, off, 16));
        }
        if (tn == 0) {
            atomicAdd(&g_sum[o], s);
            atomicAdd(&g_sumsq[o], s2);
            unsigned umx = __float_as_uint(mx);
            umx = (umx & 0x80000000u) ? ~umx : (umx | 0x80000000u);
            atomicMax(&g_ymax[b512 + o], umx);
            unsigned umn = __float_as_uint(mn);
            umn = (umn & 0x80000000u) ? ~umn : (umn | 0x80000000u);
            atomicMin(&g_ymin[b512 + o], umn);
        }
    }
}

// ---------------- zero BN accumulators (edge layers) ----------------
__global__ void zero_stats() {
    int t = blockIdx.x * 256 + threadIdx.x;
    if (t < 512) { g_sum[t] = 0.f; g_sumsq[t] = 0.f; }
}

// ---------------- init for gemm5 stage: sums + ymax/ymin ----------------
__global__ void init5_kernel() {
    int t = blockIdx.x * 256 + threadIdx.x;
    if (t < 512) { g_sum[t] = 0.f; g_sumsq[t] = 0.f; }
    if (t < BB * 512) { g_ymax[t] = 0u; g_ymin[t] = 0xFFFFFFFFu; }
}

// ---------------- BN stats edge: 1024-thread blocks, A row staged 2x (R13-exact) ------------
__global__ __launch_bounds__(1024) void stats_edge(int O) {
    __shared__ float sA[NN];                 // 8 KB: the A[b][o][*] row
    __shared__ float ss[1024], ss2[1024];
    int b = blockIdx.z, o = blockIdx.y;
    int tid = threadIdx.x;
    int n = blockIdx.x * 1024 + tid;
    size_t rowoff = ((size_t)b * O + o) * NN;
    const float* __restrict__ Arow = g_A + rowoff;
    if (tid < NN / 4)
        reinterpret_cast<float4*>(sA)[tid] = reinterpret_cast<const float4*>(Arow)[tid];
    float cv = g_Cc[rowoff + n];
    const int* __restrict__ ip = g_idx + ((size_t)b * NN + n) * KK;
    int idx[KK];
    #pragma unroll
    for (int k = 0; k < KK; k++) idx[k] = ip[k];
    __syncthreads();
    float s = 0.f, s2 = 0.f, mx = -3.4e38f, mn = 3.4e38f;
    #pragma unroll
    for (int k = 0; k < KK; k++) {
        float v = sA[idx[k]] + cv;
        s += v; s2 += v * v;
        mx = fmaxf(mx, v); mn = fminf(mn, v);
    }
    float* vmax = g_dist;
    float* vmin = g_dist + (size_t)BB * 256 * NN;
    vmax[rowoff + n] = mx;
    vmin[rowoff + n] = mn;
    ss[tid] = s; ss2[tid] = s2;
    __syncthreads();
    for (int st = 512; st > 0; st >>= 1) {
        if (tid < st) {
            ss[tid] += ss[tid + st];
            ss2[tid] += ss2[tid + st];
        }
        __syncthreads();
    }
    if (tid == 0) { atomicAdd(&g_sum[o], ss[0]); atomicAdd(&g_sumsq[o], ss2[0]); }
}

// ---------------- finalize BN scale/shift ----------------
__global__ void finalize_bn(const float* __restrict__ gam, const float* __restrict__ bet,
                            float inv_cnt, int O) {
    int o = blockIdx.x * 256 + threadIdx.x;
    if (o >= O) return;
    float mean = g_sum[o] * inv_cnt;
    float var = g_sumsq[o] * inv_cnt - mean * mean;
    float sc = gam[o] * rsqrtf(var + 1e-5f);
    g_scale[o] = sc;
    g_shift[o] = bet[o] - mean * sc;
}

// ---------------- BN apply + leakyReLU + max over k (R9-exact elementwise) ----------------
__global__ __launch_bounds__(256) void apply_edge(int O, int coff) {
    int i = blockIdx.x * 256 + threadIdx.x;       // (b*O+o)*NN + n
    int n = i & (NN - 1);
    int bo = i >> 11;
    int o = bo % O, b = bo / O;
    float sc = g_scale[o], sh = g_shift[o];
    const float* vmax = g_dist;
    const float* vmin = g_dist + (size_t)BB * 256 * NN;
    float v = (sc >= 0.f) ? vmax[i] : vmin[i];
    v = v * sc + sh;
    v = (v > 0.f) ? v : 0.2f * v;
    g_xcat[((size_t)b * 512 + coff + o) * NN + n] = v;
}

// ---------------- pool5: decode per-(b,o) max/min key, BN apply + lrelu -> pooled/feat ------
__global__ void pool5(float* __restrict__ out) {
    int i = blockIdx.x * 256 + threadIdx.x;       // b*512 + o
    if (i >= BB * 512) return;
    int o = i & 511;
    float sc = g_scale[o], sh = g_shift[o];
    unsigned k = (sc >= 0.f) ? g_ymax[i] : g_ymin[i];
    unsigned u = (k & 0x80000000u) ? (k & 0x7FFFFFFFu) : ~k;
    float v = __uint_as_float(u);
    v = v * sc + sh;
    v = (v > 0.f) ? v : 0.2f * v;
    g_pooled[i] = v;
    out[i] = v;                                   // feat (B,1,512)
}

// ---------------- embedding + clustering ----------------
__global__ __launch_bounds__(256) void final_kernel(const float* __restrict__ w_emb,
                                                    const float* __restrict__ w_clu,
                                                    float* __restrict__ out) {
    __shared__ float sp[BB * 512];
    __shared__ float se[BB * 128];
    __shared__ float sq[BB * 10];
    __shared__ float ssum[BB];
    int t = threadIdx.x;
    for (int i = t; i < BB * 512; i += 256) sp[i] = g_pooled[i];
    __syncthreads();
    for (int i = t; i < BB * 128; i += 256) {
        int b = i >> 7, f = i & 127;
        float s = 0.f;
        for (int o = 0; o < 512; o++) s += sp[b * 512 + o] * w_emb[(size_t)f * 512 + o];
        se[i] = s;
        out[BB * 512 + i] = s;                    // embedding (B,128)
    }
    __syncthreads();
    if (t < 80) {
        int b = t / 10, c = t % 10;
        float d2 = 0.f;
        for (int f = 0; f < 128; f++) {
            float dd = se[b * 128 + f] - w_clu[c * 128 + f];
            d2 += dd * dd;
        }
        sq[t] = 1.0f / (1.0f + d2);               // alpha=1 -> power -1
    }
    __syncthreads();
    if (t < 8) {
        float s = 0.f;
        for (int c = 0; c < 10; c++) s += sq[t * 10 + c];
        ssum[t] = s;
    }
    __syncthreads();
    if (t < 80) out[BB * 512 + BB * 128 + t] = sq[t] / ssum[t / 10];
}

// ---------------- host launch (R9 schedule: KNN chain forked onto a second stream) ----------
static cudaStream_t g_sA = nullptr;
static cudaEvent_t g_evF[4], g_evK[4];

static void run_block(int layer, const float* Xsrc, int bstride, int Cin,
                      const float* W, const float* gam, const float* bet,
                      int O, int coff) {
    // fork: KNN chain (xx -> dist -> topk) on stream A; edge_gemm + zero_stats on default
    cudaEventRecord(g_evF[layer], 0);
    cudaStreamWaitEvent(g_sA, g_evF[layer], 0);
    xx_kernel<<<BB * NN / 256, 256, 0, g_sA>>>(Xsrc, Cin, bstride);
    dim3 dg(NPAIR, 1, BB);
    knn_dist_kernel<<<dg, 256, 0, g_sA>>>(Xsrc, Cin, bstride);
    topk_kernel<<<BB * NN / TPW, 32 * TPW, 0, g_sA>>>();
    cudaEventRecord(g_evK[layer], g_sA);

    dim3 eg(NN / 64, O / 64, BB);
    edge_gemm_kernel<<<eg, 256>>>(W, Xsrc, Cin, O, bstride);
    zero_stats<<<2, 256>>>();

    // join: stats needs both g_idx (stream A) and A/Cc (default)
    cudaStreamWaitEvent(0, g_evK[layer], 0);
    dim3 sg(NN / 1024, O, BB);
    stats_edge<<<sg, 1024>>>(O);
    finalize_bn<<<(O + 255) / 256, 256>>>(gam, bet, 1.0f / (float)(BB * NN * KK), O);
    apply_edge<<<(BB * O * NN) / 256, 256>>>(O, coff);
}

extern "C" void kernel_launch(void* const* d_in, const int* in_sizes, int n_in,
                              void* d_out, int out_size) {
    const float* x     = (const float*)d_in[0];
    const float* w1    = (const float*)d_in[1];
    const float* g1    = (const float*)d_in[2];
    const float* b1    = (const float*)d_in[3];
    const float* w2    = (const float*)d_in[4];
    const float* g2    = (const float*)d_in[5];
    const float* b2    = (const float*)d_in[6];
    const float* w3    = (const float*)d_in[7];
    const float* g3    = (const float*)d_in[8];
    const float* b3    = (const float*)d_in[9];
    const float* w4    = (const float*)d_in[10];
    const float* g4    = (const float*)d_in[11];
    const float* b4    = (const float*)d_in[12];
    const float* w5    = (const float*)d_in[13];
    const float* g5    = (const float*)d_in[14];
    const float* b5    = (const float*)d_in[15];
    const float* wemb  = (const float*)d_in[16];
    const float* wclu  = (const float*)d_in[17];
    float* out = (float*)d_out;

    static float* p_xt = nullptr;
    static float* p_xcat = nullptr;
    if (!p_xt) {
        cudaGetSymbolAddress((void**)&p_xt, g_xt);
        cudaGetSymbolAddress((void**)&p_xcat, g_xcat);
        cudaStreamCreateWithFlags(&g_sA, cudaStreamNonBlocking);
        for (int l = 0; l < 4; l++) {
            cudaEventCreateWithFlags(&g_evF[l], cudaEventDisableTiming);
            cudaEventCreateWithFlags(&g_evK[l], cudaEventDisableTiming);
        }
    }

    xt_kernel<<<BB * NN / 256, 256>>>(x);

    run_block(0, p_xt,              3 * NN,   3,   w1, g1, b1,  64, 0);
    run_block(1, p_xcat,            512 * NN, 64,  w2, g2, b2,  64, 64);
    run_block(2, p_xcat + 64 * NN,  512 * NN, 64,  w3, g3, b3, 128, 128);
    run_block(3, p_xcat + 128 * NN, 512 * NN, 128, w4, g4, b4, 256, 256);

    init5_kernel<<<(BB * 512 + 255) / 256, 256>>>();
    dim3 gg5(NN / 128, 512 / 128, BB);
    gemm5_kernel<<<gg5, 256>>>(w5);
    finalize_bn<<<2, 256>>>(g5, b5, 1.0f / (float)(BB * NN), 512);
    pool5<<<(BB * 512 + 255) / 256, 256>>>(out);
    final_kernel<<<1, 256>>>(wemb, wclu, out);
}

// round 15
// speedup vs baseline: 1.0065x; 1.0065x over previous
#include <cuda_runtime.h>
#include <cstdint>

#define BB 8
#define NN 2048
#define KK 20
#define TPW 4    // rows (warps) per topk block
#define NT (NN / 128)            // 16 tiles per dim
#define NPAIR (NT * (NT + 1) / 2) // 136 upper-tri tile pairs

// ---------------- static scratch (no runtime allocation allowed) ----------------
__device__ float g_xt[BB * 3 * NN];
__device__ float g_xx[BB * NN];
__device__ float g_dist[(size_t)BB * NN * NN];          // 134 MB (also reused as vmax/vmin scratch)
__device__ int   g_idx[BB * NN * KK];
__device__ float g_A[(size_t)BB * 256 * NN];            // [b][o][n] 16 MB
__device__ float g_Cc[(size_t)BB * 256 * NN];           // [b][o][n] 16 MB
__device__ float g_xcat[(size_t)BB * 512 * NN];         // [b][c][n] 33 MB (x1|x2|x3|x4)
__device__ float g_sum[512];
__device__ float g_sumsq[512];
__device__ float g_scale[512];
__device__ float g_shift[512];
__device__ float g_pooled[BB * 512];
__device__ unsigned g_ymax[BB * 512];
__device__ unsigned g_ymin[BB * 512];

// ---------------- transpose x (B,N,3) -> (B,3,N) ----------------
__global__ void xt_kernel(const float* __restrict__ x) {
    int i = blockIdx.x * 256 + threadIdx.x;       // b*NN + n
    if (i >= BB * NN) return;
    int b = i >> 11, n = i & (NN - 1);
    #pragma unroll
    for (int c = 0; c < 3; c++)
        g_xt[(b * 3 + c) * NN + n] = x[(size_t)i * 3 + c];
}

// ---------------- squared norms per point ----------------
__global__ void xx_kernel(const float* __restrict__ Xall, int C, int bstride) {
    int i = blockIdx.x * 256 + threadIdx.x;       // b*NN + n
    int b = i >> 11, n = i & (NN - 1);
    const float* X = Xall + (size_t)b * bstride + n;
    float s = 0.f;
    for (int c = 0; c < C; c++) { float v = X[(size_t)c * NN]; s += v * v; }
    g_xx[i] = s;
}

// ---------------- distance matrix: SYMMETRIC upper-tri tile pairs (R12-exact) ----------------
__global__ __launch_bounds__(256) void knn_dist_kernel(const float* __restrict__ Xall,
                                                       int C, int bstride) {
    int b = blockIdx.z;
    const float* X = Xall + (size_t)b * bstride;
    const float* xxr = g_xx + b * NN;
    float* D = g_dist + (size_t)b * NN * NN;

    // decode upper-tri pair (ti <= tj)
    int pair = blockIdx.x;
    int ti = 0, remp = pair;
    while (remp >= NT - ti) { remp -= NT - ti; ti++; }
    int tj = ti + remp;
    int n0 = ti * 128, m0 = tj * 128;

    __shared__ float Ns[2][8][132];
    __shared__ float Ms[2][8][132];
    __shared__ float Ts[32][132];                  // slab transpose buffer
    int t = threadIdx.x;
    int to = t >> 4, tn = t & 15;
    int lk = (t * 4) >> 7, lc = (t * 4) & 127;     // this thread's load slot
    float acc[8][8] = {};
    int nch = (C + 7) / 8;

    // preload chunk 0
    {
        float4 vn = make_float4(0.f, 0.f, 0.f, 0.f), vm = vn;
        if (lk < C) {
            vn = *reinterpret_cast<const float4*>(&X[(size_t)lk * NN + n0 + lc]);
            vm = *reinterpret_cast<const float4*>(&X[(size_t)lk * NN + m0 + lc]);
        }
        *reinterpret_cast<float4*>(&Ns[0][lk][lc]) = vn;
        *reinterpret_cast<float4*>(&Ms[0][lk][lc]) = vm;
    }
    __syncthreads();

    for (int ch = 0; ch < nch; ch++) {
        int cur = ch & 1;
        float4 pn = make_float4(0.f, 0.f, 0.f, 0.f), pm = pn;
        if (ch + 1 < nch) {
            int kg = (ch + 1) * 8 + lk;
            if (kg < C) {
                pn = *reinterpret_cast<const float4*>(&X[(size_t)kg * NN + n0 + lc]);
                pm = *reinterpret_cast<const float4*>(&X[(size_t)kg * NN + m0 + lc]);
            }
        }
        #pragma unroll
        for (int k = 0; k < 8; k++) {
            float a[8], bb_[8];
            *reinterpret_cast<float4*>(&a[0]) = *reinterpret_cast<const float4*>(&Ns[cur][k][to * 8]);
            *reinterpret_cast<float4*>(&a[4]) = *reinterpret_cast<const float4*>(&Ns[cur][k][to * 8 + 4]);
            *reinterpret_cast<float4*>(&bb_[0]) = *reinterpret_cast<const float4*>(&Ms[cur][k][tn * 8]);
            *reinterpret_cast<float4*>(&bb_[4]) = *reinterpret_cast<const float4*>(&Ms[cur][k][tn * 8 + 4]);
            #pragma unroll
            for (int i = 0; i < 8; i++)
                #pragma unroll
                for (int j = 0; j < 8; j++)
                    acc[i][j] += a[i] * bb_[j];
        }
        __syncthreads();
        if (ch + 1 < nch) {
            *reinterpret_cast<float4*>(&Ns[cur ^ 1][lk][lc]) = pn;
            *reinterpret_cast<float4*>(&Ms[cur ^ 1][lk][lc]) = pm;
            __syncthreads();
        }
    }

    // direct tile write (rows n, cols m)
    #pragma unroll
    for (int i = 0; i < 8; i++) {
        int n = n0 + to * 8 + i;
        float xn = xxr[n];
        #pragma unroll
        for (int jj = 0; jj < 2; jj++) {
            float4 v4;
            float* vp = &v4.x;
            #pragma unroll
            for (int j = 0; j < 4; j++) {
                int m = m0 + tn * 8 + jj * 4 + j;
                float v = 2.0f * acc[i][jj * 4 + j] - xn;  // diag: 2v - v = v exactly
                vp[j] = v - xxr[m];                        // diag: v - v = 0 exactly
            }
            *reinterpret_cast<float4*>(&D[(size_t)n * NN + m0 + tn * 8 + jj * 4]) = v4;
        }
    }

    // mirrored tile write (rows m, cols n) via 32-row slab transpose in smem
    if (ti != tj) {
        #pragma unroll
        for (int p = 0; p < 4; p++) {
            __syncthreads();                       // protect Ts from previous slab reads
            if ((tn >> 2) == p) {
                int lt = tn & 3;
                #pragma unroll
                for (int j = 0; j < 8; j++) {
                    int m = m0 + tn * 8 + j;
                    float xm = xxr[m];
                    #pragma unroll
                    for (int i = 0; i < 8; i++) {
                        int n = n0 + to * 8 + i;
                        float v = 2.0f * acc[i][j] - xm;   // mirror: xx[m] first
                        Ts[lt * 8 + j][to * 8 + i] = v - xxr[n];
                    }
                }
            }
            __syncthreads();
            int lm = t >> 3;                        // 0..31
            int c0 = (t & 7) * 16;
            int mg = m0 + p * 32 + lm;
            float* drow = &D[(size_t)mg * NN + n0 + c0];
            #pragma unroll
            for (int q = 0; q < 4; q++)
                *reinterpret_cast<float4*>(&drow[q * 4]) =
                    *reinterpret_cast<const float4*>(&Ts[lm][c0 + q * 4]);
        }
    }
}

// ---------------- top-K: warp-per-row radix select; keys split regs(32)+smem(32) ------------
// Iteration order, element->lane mapping, and output-slot logic identical to R14 —
// g_idx is byte-identical; only key storage location changed (lower regs -> higher occ).
__global__ __launch_bounds__(32 * TPW) void topk_kernel() {
    __shared__ unsigned hist[TPW][256];
    __shared__ int cand[TPW][64];
    __shared__ unsigned skey[TPW][32][32];   // [warp][r-32][lane], 16 KB, conflict-free
    int warp = threadIdx.x >> 5, lane = threadIdx.x & 31;
    int row = blockIdx.x * TPW + warp;       // b*NN + n
    const float4* D4 = reinterpret_cast<const float4*>(g_dist + (size_t)row * NN);
    unsigned lmask_lt = (1u << lane) - 1u;

    // keys: key[r] (r<32) in regs; r>=32 in skey. Element i = (r>>2)*128 + lane*4 + (r&3).
    unsigned key[32];
    #pragma unroll
    for (int j = 0; j < 16; j++) {
        float4 d4 = D4[j * 32 + lane];
        const float* dp = &d4.x;
        #pragma unroll
        for (int q = 0; q < 4; q++) {
            unsigned u = __float_as_uint(dp[q]);
            unsigned k = (u & 0x80000000u) ? ~u : (u | 0x80000000u);
            if (j < 8) key[j * 4 + q] = k;
            else       skey[warp][(j - 8) * 4 + q][lane] = k;
        }
    }
    __syncwarp();

    unsigned prefix = 0; int rem = KK;
    #pragma unroll
    for (int pass = 0; pass < 4; pass++) {
        int shift = 24 - 8 * pass;
        #pragma unroll
        for (int j = lane; j < 256; j += 32) hist[warp][j] = 0;
        __syncwarp();
        #pragma unroll
        for (int r = 0; r < 32; r++) {
            unsigned k = key[r];
            if (pass == 0 || (k >> (shift + 8)) == prefix)
                atomicAdd(&hist[warp][(k >> shift) & 0xFF], 1u);
        }
        #pragma unroll
        for (int r = 32; r < 64; r++) {
            unsigned k = skey[warp][r - 32][lane];
            if (pass == 0 || (k >> (shift + 8)) == prefix)
                atomicAdd(&hist[warp][(k >> shift) & 0xFF], 1u);
        }
        __syncwarp();
        int base = 255 - lane * 8;
        unsigned h[8]; unsigned s = 0;
        #pragma unroll
        for (int j = 0; j < 8; j++) { h[j] = hist[warp][base - j]; s += h[j]; }
        unsigned pre = s;
        #pragma unroll
        for (int off = 1; off < 32; off <<= 1) {
            unsigned v = __shfl_up_sync(0xffffffffu, pre, off);
            if (lane >= off) pre += v;
        }
        unsigned excl = pre - s;
        bool owner = (excl < (unsigned)rem) && ((unsigned)rem <= excl + s);
        unsigned m = __ballot_sync(0xffffffffu, owner);
        int ol = __ffs(m) - 1;
        unsigned nb = 0; int nrem = 0;
        if (owner) {
            unsigned cum = excl;
            #pragma unroll
            for (int j = 0; j < 8; j++) {
                if (cum + h[j] >= (unsigned)rem) { nb = (unsigned)(base - j); nrem = rem - (int)cum; break; }
                cum += h[j];
            }
        }
        nb = __shfl_sync(0xffffffffu, nb, ol);
        nrem = __shfl_sync(0xffffffffu, nrem, ol);
        prefix = (prefix << 8) | nb;
        rem = nrem;
        __syncwarp();
    }

    unsigned T = prefix;                 // key of the 20th largest
    int* outp = &g_idx[(size_t)row * KK];
    int baseG = 0, baseC = 0;
    #pragma unroll
    for (int r = 0; r < 64; r++) {
        unsigned k = (r < 32) ? key[r] : skey[warp][r - 32][lane];
        bool g = (k > T), e = (k == T);
        unsigned mg = __ballot_sync(0xffffffffu, g);
        unsigned me = __ballot_sync(0xffffffffu, e);
        int i = (r >> 2) * 128 + lane * 4 + (r & 3);
        if (g) outp[baseG + __popc(mg & lmask_lt)] = i;
        if (e) {
            int c = baseC + __popc(me & lmask_lt);
            if (c < 64) cand[warp][c] = i;
        }
        baseG += __popc(mg);
        baseC += __popc(me);
    }
    __syncwarp();
    if (lane == 0) {
        int base = baseG;
        int cc = baseC;
        if (cc == rem) {
            for (int i = 0; i < rem; i++) outp[base + i] = cand[warp][i];
        } else if (cc <= 64) {
            for (int r = 0; r < rem; r++) {          // ties: lowest indices
                int best = NN, bi = -1;
                for (int i = 0; i < cc; i++)
                    if (cand[warp][i] < best) { best = cand[warp][i]; bi = i; }
                outp[base + r] = best;
                cand[warp][bi] = NN;
            }
        } else {                                     // pathological: many exact ties
            const float* D = g_dist + (size_t)row * NN;
            int got = 0;
            for (int i = 0; i < NN && got < rem; i++) {
                unsigned u = __float_as_uint(D[i]);
                unsigned k = (u & 0x80000000u) ? ~u : (u | 0x80000000u);
                if (k == T) outp[base + got++] = i;
            }
        }
    }
}

// ---------------- edge GEMM: A[o][n] = Wl@X, Cc[o][n] = (Wr-Wl)@X  (R9-exact) ----------------
__global__ __launch_bounds__(256) void edge_gemm_kernel(const float* __restrict__ W,
                                                        const float* __restrict__ Xall,
                                                        int C, int O, int bstride) {
    int b = blockIdx.z;
    const float* X = Xall + (size_t)b * bstride;
    float* Aout = g_A + (size_t)b * O * NN;
    float* Cout = g_Cc + (size_t)b * O * NN;
    int o0 = blockIdx.y * 64, n0 = blockIdx.x * 64;
    __shared__ float Xs[16][68];
    __shared__ float Wl[16][68];
    __shared__ float Wd[16][68];
    int t = threadIdx.x;
    int to = t >> 4, tn = t & 15;
    float accA[4][4] = {}, accC[4][4] = {};
    int C2 = 2 * C;
    for (int kk = 0; kk < C; kk += 16) {
        for (int i = t; i < 16 * 64; i += 256) {
            int k = i & 15, o = i >> 4;
            float wl = 0.f, wr = 0.f;
            if (kk + k < C) {
                wl = W[(size_t)(o0 + o) * C2 + kk + k];
                wr = W[(size_t)(o0 + o) * C2 + C + kk + k];
            }
            Wl[k][o] = wl; Wd[k][o] = wr - wl;
        }
        for (int i = t; i < 16 * 64; i += 256) {
            int k = i >> 6, n = i & 63;
            Xs[k][n] = (kk + k < C) ? X[(size_t)(kk + k) * NN + n0 + n] : 0.f;
        }
        __syncthreads();
        #pragma unroll
        for (int k = 0; k < 16; k++) {
            float4 wo4 = *reinterpret_cast<const float4*>(&Wl[k][to * 4]);
            float4 wd4 = *reinterpret_cast<const float4*>(&Wd[k][to * 4]);
            float4 xv4 = *reinterpret_cast<const float4*>(&Xs[k][tn * 4]);
            const float* wo = &wo4.x;
            const float* wd = &wd4.x;
            const float* xv = &xv4.x;
            #pragma unroll
            for (int i = 0; i < 4; i++)
                #pragma unroll
                for (int j = 0; j < 4; j++) {
                    accA[i][j] += wo[i] * xv[j];
                    accC[i][j] += wd[i] * xv[j];
                }
        }
        __syncthreads();
    }
    #pragma unroll
    for (int i = 0; i < 4; i++) {
        int o = o0 + to * 4 + i;
        float4 a4, c4;
        #pragma unroll
        for (int j = 0; j < 4; j++) { (&a4.x)[j] = accA[i][j]; (&c4.x)[j] = accC[i][j]; }
        *reinterpret_cast<float4*>(&Aout[(size_t)o * NN + n0 + tn * 4]) = a4;
        *reinterpret_cast<float4*>(&Cout[(size_t)o * NN + n0 + tn * 4]) = c4;
    }
}

// ---------------- gemm5: 128x128 tile, 8x8 micro-tile, fused stats epilogue (R13-exact) -----
__global__ __launch_bounds__(256) void gemm5_kernel(const float* __restrict__ W) {
    int b = blockIdx.z;
    const float* X = g_xcat + (size_t)b * 512 * NN;
    int o0 = blockIdx.y * 128, n0 = blockIdx.x * 128;
    __shared__ float Xs[2][8][132];
    __shared__ float Ws[2][8][132];
    int t = threadIdx.x;
    int to = t >> 4, tn = t & 15;
    int lo = t & 127, lhalf = (t >> 7) * 4;
    int lk = (t * 4) >> 7, ln = (t * 4) & 127;
    float acc[8][8] = {};

    // preload chunk 0
    {
        float4 w4 = *reinterpret_cast<const float4*>(&W[(size_t)(o0 + lo) * 512 + lhalf]);
        const float* wp = &w4.x;
        #pragma unroll
        for (int q = 0; q < 4; q++) Ws[0][lhalf + q][lo] = wp[q];
        *reinterpret_cast<float4*>(&Xs[0][lk][ln]) =
            *reinterpret_cast<const float4*>(&X[(size_t)lk * NN + n0 + ln]);
    }
    __syncthreads();

    for (int ch = 0; ch < 64; ch++) {
        int cur = ch & 1;
        float4 pw = make_float4(0.f, 0.f, 0.f, 0.f), px = pw;
        if (ch + 1 < 64) {
            int kk = (ch + 1) * 8;
            pw = *reinterpret_cast<const float4*>(&W[(size_t)(o0 + lo) * 512 + kk + lhalf]);
            px = *reinterpret_cast<const float4*>(&X[(size_t)(kk + lk) * NN + n0 + ln]);
        }
        #pragma unroll
        for (int k = 0; k < 8; k++) {
            float a[8], x_[8];
            *reinterpret_cast<float4*>(&a[0]) = *reinterpret_cast<const float4*>(&Ws[cur][k][to * 8]);
            *reinterpret_cast<float4*>(&a[4]) = *reinterpret_cast<const float4*>(&Ws[cur][k][to * 8 + 4]);
            *reinterpret_cast<float4*>(&x_[0]) = *reinterpret_cast<const float4*>(&Xs[cur][k][tn * 8]);
            *reinterpret_cast<float4*>(&x_[4]) = *reinterpret_cast<const float4*>(&Xs[cur][k][tn * 8 + 4]);
            #pragma unroll
            for (int i = 0; i < 8; i++)
                #pragma unroll
                for (int j = 0; j < 8; j++)
                    acc[i][j] += a[i] * x_[j];
        }
        __syncthreads();
        if (ch + 1 < 64) {
            const float* wp = &pw.x;
            #pragma unroll
            for (int q = 0; q < 4; q++) Ws[cur ^ 1][lhalf + q][lo] = wp[q];
            *reinterpret_cast<float4*>(&Xs[cur ^ 1][lk][ln]) = px;
            __syncthreads();
        }
    }

    // epilogue: per-o-row stats over this tile's 128 n-cols (16-lane shuffle reduce)
    int b512 = b * 512;
    #pragma unroll
    for (int i = 0; i < 8; i++) {
        int o = o0 + to * 8 + i;
        float s = 0.f, s2 = 0.f, mx = -3.4e38f, mn = 3.4e38f;
        #pragma unroll
        for (int j = 0; j < 8; j++) {
            float v = acc[i][j];
            s += v; s2 += v * v;
            mx = fmaxf(mx, v); mn = fminf(mn, v);
        }
        #pragma unroll
        for (int off = 8; off > 0; off >>= 1) {
            s  += __shfl_down_sync(0xffffffffu, s, off, 16);
            s2 += __shfl_down_sync(0xffffffffu, s2, off, 16);
            mx = fmaxf(mx, __shfl_down_sync(0xffffffffu, mx, off, 16));
            mn = fminf(mn, __shfl_down_sync(0xffffffffu, mn, off, 16));
        }
        if (tn == 0) {
            atomicAdd(&g_sum[o], s);
            atomicAdd(&g_sumsq[o], s2);
            unsigned umx = __float_as_uint(mx);
            umx = (umx & 0x80000000u) ? ~umx : (umx | 0x80000000u);
            atomicMax(&g_ymax[b512 + o], umx);
            unsigned umn = __float_as_uint(mn);
            umn = (umn & 0x80000000u) ? ~umn : (umn | 0x80000000u);
            atomicMin(&g_ymin[b512 + o], umn);
        }
    }
}

// ---------------- zero BN accumulators (edge layers) ----------------
__global__ void zero_stats() {
    int t = blockIdx.x * 256 + threadIdx.x;
    if (t < 512) { g_sum[t] = 0.f; g_sumsq[t] = 0.f; }
}

// ---------------- init for gemm5 stage: sums + ymax/ymin ----------------
__global__ void init5_kernel() {
    int t = blockIdx.x * 256 + threadIdx.x;
    if (t < 512) { g_sum[t] = 0.f; g_sumsq[t] = 0.f; }
    if (t < BB * 512) { g_ymax[t] = 0u; g_ymin[t] = 0xFFFFFFFFu; }
}

// ---------------- BN stats edge: 1024-thread blocks, A row staged 2x (R13-exact) ------------
__global__ __launch_bounds__(1024) void stats_edge(int O) {
    __shared__ float sA[NN];                 // 8 KB: the A[b][o][*] row
    __shared__ float ss[1024], ss2[1024];
    int b = blockIdx.z, o = blockIdx.y;
    int tid = threadIdx.x;
    int n = blockIdx.x * 1024 + tid;
    size_t rowoff = ((size_t)b * O + o) * NN;
    const float* __restrict__ Arow = g_A + rowoff;
    if (tid < NN / 4)
        reinterpret_cast<float4*>(sA)[tid] = reinterpret_cast<const float4*>(Arow)[tid];
    float cv = g_Cc[rowoff + n];
    const int* __restrict__ ip = g_idx + ((size_t)b * NN + n) * KK;
    int idx[KK];
    #pragma unroll
    for (int k = 0; k < KK; k++) idx[k] = ip[k];
    __syncthreads();
    float s = 0.f, s2 = 0.f, mx = -3.4e38f, mn = 3.4e38f;
    #pragma unroll
    for (int k = 0; k < KK; k++) {
        float v = sA[idx[k]] + cv;
        s += v; s2 += v * v;
        mx = fmaxf(mx, v); mn = fminf(mn, v);
    }
    float* vmax = g_dist;
    float* vmin = g_dist + (size_t)BB * 256 * NN;
    vmax[rowoff + n] = mx;
    vmin[rowoff + n] = mn;
    ss[tid] = s; ss2[tid] = s2;
    __syncthreads();
    for (int st = 512; st > 0; st >>= 1) {
        if (tid < st) {
            ss[tid] += ss[tid + st];
            ss2[tid] += ss2[tid + st];
        }
        __syncthreads();
    }
    if (tid == 0) { atomicAdd(&g_sum[o], ss[0]); atomicAdd(&g_sumsq[o], ss2[0]); }
}

// ---------------- finalize BN scale/shift ----------------
__global__ void finalize_bn(const float* __restrict__ gam, const float* __restrict__ bet,
                            float inv_cnt, int O) {
    int o = blockIdx.x * 256 + threadIdx.x;
    if (o >= O) return;
    float mean = g_sum[o] * inv_cnt;
    float var = g_sumsq[o] * inv_cnt - mean * mean;
    float sc = gam[o] * rsqrtf(var + 1e-5f);
    g_scale[o] = sc;
    g_shift[o] = bet[o] - mean * sc;
}

// ---------------- BN apply + leakyReLU + max over k (R9-exact elementwise) ----------------
__global__ __launch_bounds__(256) void apply_edge(int O, int coff) {
    int i = blockIdx.x * 256 + threadIdx.x;       // (b*O+o)*NN + n
    int n = i & (NN - 1);
    int bo = i >> 11;
    int o = bo % O, b = bo / O;
    float sc = g_scale[o], sh = g_shift[o];
    const float* vmax = g_dist;
    const float* vmin = g_dist + (size_t)BB * 256 * NN;
    float v = (sc >= 0.f) ? vmax[i] : vmin[i];
    v = v * sc + sh;
    v = (v > 0.f) ? v : 0.2f * v;
    g_xcat[((size_t)b * 512 + coff + o) * NN + n] = v;
}

// ---------------- pool5: decode per-(b,o) max/min key, BN apply + lrelu -> pooled/feat ------
__global__ void pool5(float* __restrict__ out) {
    int i = blockIdx.x * 256 + threadIdx.x;       // b*512 + o
    if (i >= BB * 512) return;
    int o = i & 511;
    float sc = g_scale[o], sh = g_shift[o];
    unsigned k = (sc >= 0.f) ? g_ymax[i] : g_ymin[i];
    unsigned u = (k & 0x80000000u) ? (k & 0x7FFFFFFFu) : ~k;
    float v = __uint_as_float(u);
    v = v * sc + sh;
    v = (v > 0.f) ? v : 0.2f * v;
    g_pooled[i] = v;
    out[i] = v;                                   // feat (B,1,512)
}

// ---------------- embedding + clustering ----------------
__global__ __launch_bounds__(256) void final_kernel(const float* __restrict__ w_emb,
                                                    const float* __restrict__ w_clu,
                                                    float* __restrict__ out) {
    __shared__ float sp[BB * 512];
    __shared__ float se[BB * 128];
    __shared__ float sq[BB * 10];
    __shared__ float ssum[BB];
    int t = threadIdx.x;
    for (int i = t; i < BB * 512; i += 256) sp[i] = g_pooled[i];
    __syncthreads();
    for (int i = t; i < BB * 128; i += 256) {
        int b = i >> 7, f = i & 127;
        float s = 0.f;
        for (int o = 0; o < 512; o++) s += sp[b * 512 + o] * w_emb[(size_t)f * 512 + o];
        se[i] = s;
        out[BB * 512 + i] = s;                    // embedding (B,128)
    }
    __syncthreads();
    if (t < 80) {
        int b = t / 10, c = t % 10;
        float d2 = 0.f;
        for (int f = 0; f < 128; f++) {
            float dd = se[b * 128 + f] - w_clu[c * 128 + f];
            d2 += dd * dd;
        }
        sq[t] = 1.0f / (1.0f + d2);               // alpha=1 -> power -1
    }
    __syncthreads();
    if (t < 8) {
        float s = 0.f;
        for (int c = 0; c < 10; c++) s += sq[t * 10 + c];
        ssum[t] = s;
    }
    __syncthreads();
    if (t < 80) out[BB * 512 + BB * 128 + t] = sq[t] / ssum[t / 10];
}

// ---------------- host launch (R9 schedule: KNN chain forked onto a second stream) ----------
static cudaStream_t g_sA = nullptr;
static cudaEvent_t g_evF[4], g_evK[4];

static void run_block(int layer, const float* Xsrc, int bstride, int Cin,
                      const float* W, const float* gam, const float* bet,
                      int O, int coff) {
    // fork: KNN chain (xx -> dist -> topk) on stream A; edge_gemm + zero_stats on default
    cudaEventRecord(g_evF[layer], 0);
    cudaStreamWaitEvent(g_sA, g_evF[layer], 0);
    xx_kernel<<<BB * NN / 256, 256, 0, g_sA>>>(Xsrc, Cin, bstride);
    dim3 dg(NPAIR, 1, BB);
    knn_dist_kernel<<<dg, 256, 0, g_sA>>>(Xsrc, Cin, bstride);
    topk_kernel<<<BB * NN / TPW, 32 * TPW, 0, g_sA>>>();
    cudaEventRecord(g_evK[layer], g_sA);

    dim3 eg(NN / 64, O / 64, BB);
    edge_gemm_kernel<<<eg, 256>>>(W, Xsrc, Cin, O, bstride);
    zero_stats<<<2, 256>>>();

    // join: stats needs both g_idx (stream A) and A/Cc (default)
    cudaStreamWaitEvent(0, g_evK[layer], 0);
    dim3 sg(NN / 1024, O, BB);
    stats_edge<<<sg, 1024>>>(O);
    finalize_bn<<<(O + 255) / 256, 256>>>(gam, bet, 1.0f / (float)(BB * NN * KK), O);
    apply_edge<<<(BB * O * NN) / 256, 256>>>(O, coff);
}

extern "C" void kernel_launch(void* const* d_in, const int* in_sizes, int n_in,
                              void* d_out, int out_size) {
    const float* x     = (const float*)d_in[0];
    const float* w1    = (const float*)d_in[1];
    const float* g1    = (const float*)d_in[2];
    const float* b1    = (const float*)d_in[3];
    const float* w2    = (const float*)d_in[4];
    const float* g2    = (const float*)d_in[5];
    const float* b2    = (const float*)d_in[6];
    const float* w3    = (const float*)d_in[7];
    const float* g3    = (const float*)d_in[8];
    const float* b3    = (const float*)d_in[9];
    const float* w4    = (const float*)d_in[10];
    const float* g4    = (const float*)d_in[11];
    const float* b4    = (const float*)d_in[12];
    const float* w5    = (const float*)d_in[13];
    const float* g5    = (const float*)d_in[14];
    const float* b5    = (const float*)d_in[15];
    const float* wemb  = (const float*)d_in[16];
    const float* wclu  = (const float*)d_in[17];
    float* out = (float*)d_out;

    static float* p_xt = nullptr;
    static float* p_xcat = nullptr;
    if (!p_xt) {
        cudaGetSymbolAddress((void**)&p_xt, g_xt);
        cudaGetSymbolAddress((void**)&p_xcat, g_xcat);
        cudaStreamCreateWithFlags(&g_sA, cudaStreamNonBlocking);
        for (int l = 0; l < 4; l++) {
            cudaEventCreateWithFlags(&g_evF[l], cudaEventDisableTiming);
            cudaEventCreateWithFlags(&g_evK[l], cudaEventDisableTiming);
        }
    }

    xt_kernel<<<BB * NN / 256, 256>>>(x);

    run_block(0, p_xt,              3 * NN,   3,   w1, g1, b1,  64, 0);
    run_block(1, p_xcat,            512 * NN, 64,  w2, g2, b2,  64, 64);
    run_block(2, p_xcat + 64 * NN,  512 * NN, 64,  w3, g3, b3, 128, 128);
    run_block(3, p_xcat + 128 * NN, 512 * NN, 128, w4, g4, b4, 256, 256);

    init5_kernel<<<(BB * 512 + 255) / 256, 256>>>();
    dim3 gg5(NN / 128, 512 / 128, BB);
    gemm5_kernel<<<gg5, 256>>>(w5);
    finalize_bn<<<2, 256>>>(g5, b5, 1.0f / (float)(BB * NN), 512);
    pool5<<<(BB * 512 + 255) / 256, 256>>>(out);
    final_kernel<<<1, 256>>>(wemb, wclu, out);
}

// round 16
// speedup vs baseline: 1.0103x; 1.0038x over previous
#include <cuda_runtime.h>
#include <cstdint>

#define BB 8
#define NN 2048
#define KK 20
#define TPW 4    // rows (warps) per topk block
#define NT (NN / 128)            // 16 tiles per dim
#define NPAIR (NT * (NT + 1) / 2) // 136 upper-tri tile pairs
#define CLCAP 512                 // compacted candidate-list capacity per warp

// ---------------- static scratch (no runtime allocation allowed) ----------------
__device__ float g_xt[BB * 3 * NN];
__device__ float g_xx[BB * NN];
__device__ float g_dist[(size_t)BB * NN * NN];          // 134 MB (also reused as vmax/vmin scratch)
__device__ int   g_idx[BB * NN * KK];
__device__ float g_A[(size_t)BB * 256 * NN];            // [b][o][n] 16 MB
__device__ float g_Cc[(size_t)BB * 256 * NN];           // [b][o][n] 16 MB
__device__ float g_xcat[(size_t)BB * 512 * NN];         // [b][c][n] 33 MB (x1|x2|x3|x4)
__device__ float g_sum[512];
__device__ float g_sumsq[512];
__device__ float g_scale[512];
__device__ float g_shift[512];
__device__ float g_pooled[BB * 512];
__device__ unsigned g_ymax[BB * 512];
__device__ unsigned g_ymin[BB * 512];

// ---------------- transpose x (B,N,3) -> (B,3,N) ----------------
__global__ void xt_kernel(const float* __restrict__ x) {
    int i = blockIdx.x * 256 + threadIdx.x;       // b*NN + n
    if (i >= BB * NN) return;
    int b = i >> 11, n = i & (NN - 1);
    #pragma unroll
    for (int c = 0; c < 3; c++)
        g_xt[(b * 3 + c) * NN + n] = x[(size_t)i * 3 + c];
}

// ---------------- squared norms per point ----------------
__global__ void xx_kernel(const float* __restrict__ Xall, int C, int bstride) {
    int i = blockIdx.x * 256 + threadIdx.x;       // b*NN + n
    int b = i >> 11, n = i & (NN - 1);
    const float* X = Xall + (size_t)b * bstride + n;
    float s = 0.f;
    for (int c = 0; c < C; c++) { float v = X[(size_t)c * NN]; s += v * v; }
    g_xx[i] = s;
}

// ---------------- distance matrix: SYMMETRIC upper-tri tile pairs (R12-exact) ----------------
__global__ __launch_bounds__(256) void knn_dist_kernel(const float* __restrict__ Xall,
                                                       int C, int bstride) {
    int b = blockIdx.z;
    const float* X = Xall + (size_t)b * bstride;
    const float* xxr = g_xx + b * NN;
    float* D = g_dist + (size_t)b * NN * NN;

    // decode upper-tri pair (ti <= tj)
    int pair = blockIdx.x;
    int ti = 0, remp = pair;
    while (remp >= NT - ti) { remp -= NT - ti; ti++; }
    int tj = ti + remp;
    int n0 = ti * 128, m0 = tj * 128;

    __shared__ float Ns[2][8][132];
    __shared__ float Ms[2][8][132];
    __shared__ float Ts[32][132];                  // slab transpose buffer
    int t = threadIdx.x;
    int to = t >> 4, tn = t & 15;
    int lk = (t * 4) >> 7, lc = (t * 4) & 127;     // this thread's load slot
    float acc[8][8] = {};
    int nch = (C + 7) / 8;

    // preload chunk 0
    {
        float4 vn = make_float4(0.f, 0.f, 0.f, 0.f), vm = vn;
        if (lk < C) {
            vn = *reinterpret_cast<const float4*>(&X[(size_t)lk * NN + n0 + lc]);
            vm = *reinterpret_cast<const float4*>(&X[(size_t)lk * NN + m0 + lc]);
        }
        *reinterpret_cast<float4*>(&Ns[0][lk][lc]) = vn;
        *reinterpret_cast<float4*>(&Ms[0][lk][lc]) = vm;
    }
    __syncthreads();

    for (int ch = 0; ch < nch; ch++) {
        int cur = ch & 1;
        float4 pn = make_float4(0.f, 0.f, 0.f, 0.f), pm = pn;
        if (ch + 1 < nch) {
            int kg = (ch + 1) * 8 + lk;
            if (kg < C) {
                pn = *reinterpret_cast<const float4*>(&X[(size_t)kg * NN + n0 + lc]);
                pm = *reinterpret_cast<const float4*>(&X[(size_t)kg * NN + m0 + lc]);
            }
        }
        #pragma unroll
        for (int k = 0; k < 8; k++) {
            float a[8], bb_[8];
            *reinterpret_cast<float4*>(&a[0]) = *reinterpret_cast<const float4*>(&Ns[cur][k][to * 8]);
            *reinterpret_cast<float4*>(&a[4]) = *reinterpret_cast<const float4*>(&Ns[cur][k][to * 8 + 4]);
            *reinterpret_cast<float4*>(&bb_[0]) = *reinterpret_cast<const float4*>(&Ms[cur][k][tn * 8]);
            *reinterpret_cast<float4*>(&bb_[4]) = *reinterpret_cast<const float4*>(&Ms[cur][k][tn * 8 + 4]);
            #pragma unroll
            for (int i = 0; i < 8; i++)
                #pragma unroll
                for (int j = 0; j < 8; j++)
                    acc[i][j] += a[i] * bb_[j];
        }
        __syncthreads();
        if (ch + 1 < nch) {
            *reinterpret_cast<float4*>(&Ns[cur ^ 1][lk][lc]) = pn;
            *reinterpret_cast<float4*>(&Ms[cur ^ 1][lk][lc]) = pm;
            __syncthreads();
        }
    }

    // direct tile write (rows n, cols m)
    #pragma unroll
    for (int i = 0; i < 8; i++) {
        int n = n0 + to * 8 + i;
        float xn = xxr[n];
        #pragma unroll
        for (int jj = 0; jj < 2; jj++) {
            float4 v4;
            float* vp = &v4.x;
            #pragma unroll
            for (int j = 0; j < 4; j++) {
                int m = m0 + tn * 8 + jj * 4 + j;
                float v = 2.0f * acc[i][jj * 4 + j] - xn;  // diag: 2v - v = v exactly
                vp[j] = v - xxr[m];                        // diag: v - v = 0 exactly
            }
            *reinterpret_cast<float4*>(&D[(size_t)n * NN + m0 + tn * 8 + jj * 4]) = v4;
        }
    }

    // mirrored tile write (rows m, cols n) via 32-row slab transpose in smem
    if (ti != tj) {
        #pragma unroll
        for (int p = 0; p < 4; p++) {
            __syncthreads();                       // protect Ts from previous slab reads
            if ((tn >> 2) == p) {
                int lt = tn & 3;
                #pragma unroll
                for (int j = 0; j < 8; j++) {
                    int m = m0 + tn * 8 + j;
                    float xm = xxr[m];
                    #pragma unroll
                    for (int i = 0; i < 8; i++) {
                        int n = n0 + to * 8 + i;
                        float v = 2.0f * acc[i][j] - xm;   // mirror: xx[m] first
                        Ts[lt * 8 + j][to * 8 + i] = v - xxr[n];
                    }
                }
            }
            __syncthreads();
            int lm = t >> 3;                        // 0..31
            int c0 = (t & 7) * 16;
            int mg = m0 + p * 32 + lm;
            float* drow = &D[(size_t)mg * NN + n0 + c0];
            #pragma unroll
            for (int q = 0; q < 4; q++)
                *reinterpret_cast<float4*>(&drow[q * 4]) =
                    *reinterpret_cast<const float4*>(&Ts[lm][c0 + q * 4]);
        }
    }
}

// ---------------- top-K: warp-per-row radix select; pass-0 candidate compaction -------------
// Pass 0 identical. After it we know the winning bin's count (selcnt); if <= CLCAP the
// matching keys are compacted into smem and passes 1-3 scan only those. Histogram counts
// are order-independent sums -> T/rem identical; output pass unchanged -> g_idx byte-identical.
__global__ __launch_bounds__(32 * TPW) void topk_kernel() {
    __shared__ unsigned hist[TPW][256];
    __shared__ int cand[TPW][64];
    __shared__ unsigned skey[TPW][32][32];   // [warp][r-32][lane], 16 KB, conflict-free
    __shared__ unsigned cl[TPW][CLCAP];      // compacted candidate keys, 8 KB
    int warp = threadIdx.x >> 5, lane = threadIdx.x & 31;
    int row = blockIdx.x * TPW + warp;       // b*NN + n
    const float4* D4 = reinterpret_cast<const float4*>(g_dist + (size_t)row * NN);
    unsigned lmask_lt = (1u << lane) - 1u;

    // keys: key[r] (r<32) in regs; r>=32 in skey. Element i = (r>>2)*128 + lane*4 + (r&3).
    unsigned key[32];
    #pragma unroll
    for (int j = 0; j < 16; j++) {
        float4 d4 = D4[j * 32 + lane];
        const float* dp = &d4.x;
        #pragma unroll
        for (int q = 0; q < 4; q++) {
            unsigned u = __float_as_uint(dp[q]);
            unsigned k = (u & 0x80000000u) ? ~u : (u | 0x80000000u);
            if (j < 8) key[j * 4 + q] = k;
            else       skey[warp][(j - 8) * 4 + q][lane] = k;
        }
    }
    __syncwarp();

    unsigned prefix = 0; int rem = KK;
    int lcnt = 0; bool compacted = false;
    #pragma unroll
    for (int pass = 0; pass < 4; pass++) {
        int shift = 24 - 8 * pass;
        #pragma unroll
        for (int j = lane; j < 256; j += 32) hist[warp][j] = 0;
        __syncwarp();
        if (pass == 0) {
            #pragma unroll
            for (int r = 0; r < 32; r++)
                atomicAdd(&hist[warp][key[r] >> 24], 1u);
            #pragma unroll
            for (int r = 32; r < 64; r++)
                atomicAdd(&hist[warp][skey[warp][r - 32][lane] >> 24], 1u);
        } else if (compacted) {
            for (int idx = lane; idx < lcnt; idx += 32) {
                unsigned k = cl[warp][idx];
                if ((k >> (shift + 8)) == prefix)
                    atomicAdd(&hist[warp][(k >> shift) & 0xFF], 1u);
            }
        } else {
            #pragma unroll
            for (int r = 0; r < 32; r++) {
                unsigned k = key[r];
                if ((k >> (shift + 8)) == prefix)
                    atomicAdd(&hist[warp][(k >> shift) & 0xFF], 1u);
            }
            #pragma unroll
            for (int r = 32; r < 64; r++) {
                unsigned k = skey[warp][r - 32][lane];
                if ((k >> (shift + 8)) == prefix)
                    atomicAdd(&hist[warp][(k >> shift) & 0xFF], 1u);
            }
        }
        __syncwarp();
        int base = 255 - lane * 8;
        unsigned h[8]; unsigned s = 0;
        #pragma unroll
        for (int j = 0; j < 8; j++) { h[j] = hist[warp][base - j]; s += h[j]; }
        unsigned pre = s;
        #pragma unroll
        for (int off = 1; off < 32; off <<= 1) {
            unsigned v = __shfl_up_sync(0xffffffffu, pre, off);
            if (lane >= off) pre += v;
        }
        unsigned excl = pre - s;
        bool owner = (excl < (unsigned)rem) && ((unsigned)rem <= excl + s);
        unsigned m = __ballot_sync(0xffffffffu, owner);
        int ol = __ffs(m) - 1;
        unsigned nb = 0; int nrem = 0; int ncnt = 0;
        if (owner) {
            unsigned cum = excl;
            #pragma unroll
            for (int j = 0; j < 8; j++) {
                if (cum + h[j] >= (unsigned)rem) {
                    nb = (unsigned)(base - j); nrem = rem - (int)cum; ncnt = (int)h[j]; break;
                }
                cum += h[j];
            }
        }
        nb = __shfl_sync(0xffffffffu, nb, ol);
        nrem = __shfl_sync(0xffffffffu, nrem, ol);
        ncnt = __shfl_sync(0xffffffffu, ncnt, ol);
        prefix = (prefix << 8) | nb;
        rem = nrem;
        __syncwarp();

        // compact the winning bin's keys after pass 0 (counts known exactly = ncnt)
        if (pass == 0 && ncnt <= CLCAP) {
            int cbase = 0;
            #pragma unroll
            for (int r = 0; r < 64; r++) {
                unsigned k = (r < 32) ? key[r] : skey[warp][r - 32][lane];
                bool match = ((k >> 24) == prefix);
                unsigned mm = __ballot_sync(0xffffffffu, match);
                if (match) cl[warp][cbase + __popc(mm & lmask_lt)] = k;
                cbase += __popc(mm);
            }
            lcnt = ncnt;
            compacted = true;
            __syncwarp();
        }
    }

    unsigned T = prefix;                 // key of the 20th largest
    int* outp = &g_idx[(size_t)row * KK];
    int baseG = 0, baseC = 0;
    #pragma unroll
    for (int r = 0; r < 64; r++) {
        unsigned k = (r < 32) ? key[r] : skey[warp][r - 32][lane];
        bool g = (k > T), e = (k == T);
        unsigned mg = __ballot_sync(0xffffffffu, g);
        unsigned me = __ballot_sync(0xffffffffu, e);
        int i = (r >> 2) * 128 + lane * 4 + (r & 3);
        if (g) outp[baseG + __popc(mg & lmask_lt)] = i;
        if (e) {
            int c = baseC + __popc(me & lmask_lt);
            if (c < 64) cand[warp][c] = i;
        }
        baseG += __popc(mg);
        baseC += __popc(me);
    }
    __syncwarp();
    if (lane == 0) {
        int base = baseG;
        int cc = baseC;
        if (cc == rem) {
            for (int i = 0; i < rem; i++) outp[base + i] = cand[warp][i];
        } else if (cc <= 64) {
            for (int r = 0; r < rem; r++) {          // ties: lowest indices
                int best = NN, bi = -1;
                for (int i = 0; i < cc; i++)
                    if (cand[warp][i] < best) { best = cand[warp][i]; bi = i; }
                outp[base + r] = best;
                cand[warp][bi] = NN;
            }
        } else {                                     // pathological: many exact ties
            const float* D = g_dist + (size_t)row * NN;
            int got = 0;
            for (int i = 0; i < NN && got < rem; i++) {
                unsigned u = __float_as_uint(D[i]);
                unsigned k = (u & 0x80000000u) ? ~u : (u | 0x80000000u);
                if (k == T) outp[base + got++] = i;
            }
        }
    }
}

// ---------------- edge GEMM: A[o][n] = Wl@X, Cc[o][n] = (Wr-Wl)@X  (R9-exact) ----------------
__global__ __launch_bounds__(256) void edge_gemm_kernel(const float* __restrict__ W,
                                                        const float* __restrict__ Xall,
                                                        int C, int O, int bstride) {
    int b = blockIdx.z;
    const float* X = Xall + (size_t)b * bstride;
    float* Aout = g_A + (size_t)b * O * NN;
    float* Cout = g_Cc + (size_t)b * O * NN;
    int o0 = blockIdx.y * 64, n0 = blockIdx.x * 64;
    __shared__ float Xs[16][68];
    __shared__ float Wl[16][68];
    __shared__ float Wd[16][68];
    int t = threadIdx.x;
    int to = t >> 4, tn = t & 15;
    float accA[4][4] = {}, accC[4][4] = {};
    int C2 = 2 * C;
    for (int kk = 0; kk < C; kk += 16) {
        for (int i = t; i < 16 * 64; i += 256) {
            int k = i & 15, o = i >> 4;
            float wl = 0.f, wr = 0.f;
            if (kk + k < C) {
                wl = W[(size_t)(o0 + o) * C2 + kk + k];
                wr = W[(size_t)(o0 + o) * C2 + C + kk + k];
            }
            Wl[k][o] = wl; Wd[k][o] = wr - wl;
        }
        for (int i = t; i < 16 * 64; i += 256) {
            int k = i >> 6, n = i & 63;
            Xs[k][n] = (kk + k < C) ? X[(size_t)(kk + k) * NN + n0 + n] : 0.f;
        }
        __syncthreads();
        #pragma unroll
        for (int k = 0; k < 16; k++) {
            float4 wo4 = *reinterpret_cast<const float4*>(&Wl[k][to * 4]);
            float4 wd4 = *reinterpret_cast<const float4*>(&Wd[k][to * 4]);
            float4 xv4 = *reinterpret_cast<const float4*>(&Xs[k][tn * 4]);
            const float* wo = &wo4.x;
            const float* wd = &wd4.x;
            const float* xv = &xv4.x;
            #pragma unroll
            for (int i = 0; i < 4; i++)
                #pragma unroll
                for (int j = 0; j < 4; j++) {
                    accA[i][j] += wo[i] * xv[j];
                    accC[i][j] += wd[i] * xv[j];
                }
        }
        __syncthreads();
    }
    #pragma unroll
    for (int i = 0; i < 4; i++) {
        int o = o0 + to * 4 + i;
        float4 a4, c4;
        #pragma unroll
        for (int j = 0; j < 4; j++) { (&a4.x)[j] = accA[i][j]; (&c4.x)[j] = accC[i][j]; }
        *reinterpret_cast<float4*>(&Aout[(size_t)o * NN + n0 + tn * 4]) = a4;
        *reinterpret_cast<float4*>(&Cout[(size_t)o * NN + n0 + tn * 4]) = c4;
    }
}

// ---------------- gemm5: 128x128 tile, 8x8 micro-tile, fused stats epilogue (R13-exact) -----
__global__ __launch_bounds__(256) void gemm5_kernel(const float* __restrict__ W) {
    int b = blockIdx.z;
    const float* X = g_xcat + (size_t)b * 512 * NN;
    int o0 = blockIdx.y * 128, n0 = blockIdx.x * 128;
    __shared__ float Xs[2][8][132];
    __shared__ float Ws[2][8][132];
    int t = threadIdx.x;
    int to = t >> 4, tn = t & 15;
    int lo = t & 127, lhalf = (t >> 7) * 4;
    int lk = (t * 4) >> 7, ln = (t * 4) & 127;
    float acc[8][8] = {};

    // preload chunk 0
    {
        float4 w4 = *reinterpret_cast<const float4*>(&W[(size_t)(o0 + lo) * 512 + lhalf]);
        const float* wp = &w4.x;
        #pragma unroll
        for (int q = 0; q < 4; q++) Ws[0][lhalf + q][lo] = wp[q];
        *reinterpret_cast<float4*>(&Xs[0][lk][ln]) =
            *reinterpret_cast<const float4*>(&X[(size_t)lk * NN + n0 + ln]);
    }
    __syncthreads();

    for (int ch = 0; ch < 64; ch++) {
        int cur = ch & 1;
        float4 pw = make_float4(0.f, 0.f, 0.f, 0.f), px = pw;
        if (ch + 1 < 64) {
            int kk = (ch + 1) * 8;
            pw = *reinterpret_cast<const float4*>(&W[(size_t)(o0 + lo) * 512 + kk + lhalf]);
            px = *reinterpret_cast<const float4*>(&X[(size_t)(kk + lk) * NN + n0 + ln]);
        }
        #pragma unroll
        for (int k = 0; k < 8; k++) {
            float a[8], x_[8];
            *reinterpret_cast<float4*>(&a[0]) = *reinterpret_cast<const float4*>(&Ws[cur][k][to * 8]);
            *reinterpret_cast<float4*>(&a[4]) = *reinterpret_cast<const float4*>(&Ws[cur][k][to * 8 + 4]);
            *reinterpret_cast<float4*>(&x_[0]) = *reinterpret_cast<const float4*>(&Xs[cur][k][tn * 8]);
            *reinterpret_cast<float4*>(&x_[4]) = *reinterpret_cast<const float4*>(&Xs[cur][k][tn * 8 + 4]);
            #pragma unroll
            for (int i = 0; i < 8; i++)
                #pragma unroll
                for (int j = 0; j < 8; j++)
                    acc[i][j] += a[i] * x_[j];
        }
        __syncthreads();
        if (ch + 1 < 64) {
            const float* wp = &pw.x;
            #pragma unroll
            for (int q = 0; q < 4; q++) Ws[cur ^ 1][lhalf + q][lo] = wp[q];
            *reinterpret_cast<float4*>(&Xs[cur ^ 1][lk][ln]) = px;
            __syncthreads();
        }
    }

    // epilogue: per-o-row stats over this tile's 128 n-cols (16-lane shuffle reduce)
    int b512 = b * 512;
    #pragma unroll
    for (int i = 0; i < 8; i++) {
        int o = o0 + to * 8 + i;
        float s = 0.f, s2 = 0.f, mx = -3.4e38f, mn = 3.4e38f;
        #pragma unroll
        for (int j = 0; j < 8; j++) {
            float v = acc[i][j];
            s += v; s2 += v * v;
            mx = fmaxf(mx, v); mn = fminf(mn, v);
        }
        #pragma unroll
        for (int off = 8; off > 0; off >>= 1) {
            s  += __shfl_down_sync(0xffffffffu, s, off, 16);
            s2 += __shfl_down_sync(0xffffffffu, s2, off, 16);
            mx = fmaxf(mx, __shfl_down_sync(0xffffffffu, mx, off, 16));
            mn = fminf(mn, __shfl_down_sync(0xffffffffu, mn, off, 16));
        }
        if (tn == 0) {
            atomicAdd(&g_sum[o], s);
            atomicAdd(&g_sumsq[o], s2);
            unsigned umx = __float_as_uint(mx);
            umx = (umx & 0x80000000u) ? ~umx : (umx | 0x80000000u);
            atomicMax(&g_ymax[b512 + o], umx);
            unsigned umn = __float_as_uint(mn);
            umn = (umn & 0x80000000u) ? ~umn : (umn | 0x80000000u);
            atomicMin(&g_ymin[b512 + o], umn);
        }
    }
}

// ---------------- zero BN accumulators (edge layers) ----------------
__global__ void zero_stats() {
    int t = blockIdx.x * 256 + threadIdx.x;
    if (t < 512) { g_sum[t] = 0.f; g_sumsq[t] = 0.f; }
}

// ---------------- init for gemm5 stage: sums + ymax/ymin ----------------
__global__ void init5_kernel() {
    int t = blockIdx.x * 256 + threadIdx.x;
    if (t < 512) { g_sum[t] = 0.f; g_sumsq[t] = 0.f; }
    if (t < BB * 512) { g_ymax[t] = 0u; g_ymin[t] = 0xFFFFFFFFu; }
}

// ---------------- BN stats edge: 1024-thread blocks, A row staged 2x (R13-exact) ------------
__global__ __launch_bounds__(1024) void stats_edge(int O) {
    __shared__ float sA[NN];                 // 8 KB: the A[b][o][*] row
    __shared__ float ss[1024], ss2[1024];
    int b = blockIdx.z, o = blockIdx.y;
    int tid = threadIdx.x;
    int n = blockIdx.x * 1024 + tid;
    size_t rowoff = ((size_t)b * O + o) * NN;
    const float* __restrict__ Arow = g_A + rowoff;
    if (tid < NN / 4)
        reinterpret_cast<float4*>(sA)[tid] = reinterpret_cast<const float4*>(Arow)[tid];
    float cv = g_Cc[rowoff + n];
    const int* __restrict__ ip = g_idx + ((size_t)b * NN + n) * KK;
    int idx[KK];
    #pragma unroll
    for (int k = 0; k < KK; k++) idx[k] = ip[k];
    __syncthreads();
    float s = 0.f, s2 = 0.f, mx = -3.4e38f, mn = 3.4e38f;
    #pragma unroll
    for (int k = 0; k < KK; k++) {
        float v = sA[idx[k]] + cv;
        s += v; s2 += v * v;
        mx = fmaxf(mx, v); mn = fminf(mn, v);
    }
    float* vmax = g_dist;
    float* vmin = g_dist + (size_t)BB * 256 * NN;
    vmax[rowoff + n] = mx;
    vmin[rowoff + n] = mn;
    ss[tid] = s; ss2[tid] = s2;
    __syncthreads();
    for (int st = 512; st > 0; st >>= 1) {
        if (tid < st) {
            ss[tid] += ss[tid + st];
            ss2[tid] += ss2[tid + st];
        }
        __syncthreads();
    }
    if (tid == 0) { atomicAdd(&g_sum[o], ss[0]); atomicAdd(&g_sumsq[o], ss2[0]); }
}

// ---------------- finalize BN scale/shift ----------------
__global__ void finalize_bn(const float* __restrict__ gam, const float* __restrict__ bet,
                            float inv_cnt, int O) {
    int o = blockIdx.x * 256 + threadIdx.x;
    if (o >= O) return;
    float mean = g_sum[o] * inv_cnt;
    float var = g_sumsq[o] * inv_cnt - mean * mean;
    float sc = gam[o] * rsqrtf(var + 1e-5f);
    g_scale[o] = sc;
    g_shift[o] = bet[o] - mean * sc;
}

// ---------------- BN apply + leakyReLU + max over k (R9-exact elementwise) ----------------
__global__ __launch_bounds__(256) void apply_edge(int O, int coff) {
    int i = blockIdx.x * 256 + threadIdx.x;       // (b*O+o)*NN + n
    int n = i & (NN - 1);
    int bo = i >> 11;
    int o = bo % O, b = bo / O;
    float sc = g_scale[o], sh = g_shift[o];
    const float* vmax = g_dist;
    const float* vmin = g_dist + (size_t)BB * 256 * NN;
    float v = (sc >= 0.f) ? vmax[i] : vmin[i];
    v = v * sc + sh;
    v = (v > 0.f) ? v : 0.2f * v;
    g_xcat[((size_t)b * 512 + coff + o) * NN + n] = v;
}

// ---------------- pool5: decode per-(b,o) max/min key, BN apply + lrelu -> pooled/feat ------
__global__ void pool5(float* __restrict__ out) {
    int i = blockIdx.x * 256 + threadIdx.x;       // b*512 + o
    if (i >= BB * 512) return;
    int o = i & 511;
    float sc = g_scale[o], sh = g_shift[o];
    unsigned k = (sc >= 0.f) ? g_ymax[i] : g_ymin[i];
    unsigned u = (k & 0x80000000u) ? (k & 0x7FFFFFFFu) : ~k;
    float v = __uint_as_float(u);
    v = v * sc + sh;
    v = (v > 0.f) ? v : 0.2f * v;
    g_pooled[i] = v;
    out[i] = v;                                   // feat (B,1,512)
}

// ---------------- embedding + clustering ----------------
__global__ __launch_bounds__(256) void final_kernel(const float* __restrict__ w_emb,
                                                    const float* __restrict__ w_clu,
                                                    float* __restrict__ out) {
    __shared__ float sp[BB * 512];
    __shared__ float se[BB * 128];
    __shared__ float sq[BB * 10];
    __shared__ float ssum[BB];
    int t = threadIdx.x;
    for (int i = t; i < BB * 512; i += 256) sp[i] = g_pooled[i];
    __syncthreads();
    for (int i = t; i < BB * 128; i += 256) {
        int b = i >> 7, f = i & 127;
        float s = 0.f;
        for (int o = 0; o < 512; o++) s += sp[b * 512 + o] * w_emb[(size_t)f * 512 + o];
        se[i] = s;
        out[BB * 512 + i] = s;                    // embedding (B,128)
    }
    __syncthreads();
    if (t < 80) {
        int b = t / 10, c = t % 10;
        float d2 = 0.f;
        for (int f = 0; f < 128; f++) {
            float dd = se[b * 128 + f] - w_clu[c * 128 + f];
            d2 += dd * dd;
        }
        sq[t] = 1.0f / (1.0f + d2);               // alpha=1 -> power -1
    }
    __syncthreads();
    if (t < 8) {
        float s = 0.f;
        for (int c = 0; c < 10; c++) s += sq[t * 10 + c];
        ssum[t] = s;
    }
    __syncthreads();
    if (t < 80) out[BB * 512 + BB * 128 + t] = sq[t] / ssum[t / 10];
}

// ---------------- host launch (R9 schedule: KNN chain forked onto a second stream) ----------
static cudaStream_t g_sA = nullptr;
static cudaEvent_t g_evF[4], g_evK[4];

static void run_block(int layer, const float* Xsrc, int bstride, int Cin,
                      const float* W, const float* gam, const float* bet,
                      int O, int coff) {
    // fork: KNN chain (xx -> dist -> topk) on stream A; edge_gemm + zero_stats on default
    cudaEventRecord(g_evF[layer], 0);
    cudaStreamWaitEvent(g_sA, g_evF[layer], 0);
    xx_kernel<<<BB * NN / 256, 256, 0, g_sA>>>(Xsrc, Cin, bstride);
    dim3 dg(NPAIR, 1, BB);
    knn_dist_kernel<<<dg, 256, 0, g_sA>>>(Xsrc, Cin, bstride);
    topk_kernel<<<BB * NN / TPW, 32 * TPW, 0, g_sA>>>();
    cudaEventRecord(g_evK[layer], g_sA);

    dim3 eg(NN / 64, O / 64, BB);
    edge_gemm_kernel<<<eg, 256>>>(W, Xsrc, Cin, O, bstride);
    zero_stats<<<2, 256>>>();

    // join: stats needs both g_idx (stream A) and A/Cc (default)
    cudaStreamWaitEvent(0, g_evK[layer], 0);
    dim3 sg(NN / 1024, O, BB);
    stats_edge<<<sg, 1024>>>(O);
    finalize_bn<<<(O + 255) / 256, 256>>>(gam, bet, 1.0f / (float)(BB * NN * KK), O);
    apply_edge<<<(BB * O * NN) / 256, 256>>>(O, coff);
}

extern "C" void kernel_launch(void* const* d_in, const int* in_sizes, int n_in,
                              void* d_out, int out_size) {
    const float* x     = (const float*)d_in[0];
    const float* w1    = (const float*)d_in[1];
    const float* g1    = (const float*)d_in[2];
    const float* b1    = (const float*)d_in[3];
    const float* w2    = (const float*)d_in[4];
    const float* g2    = (const float*)d_in[5];
    const float* b2    = (const float*)d_in[6];
    const float* w3    = (const float*)d_in[7];
    const float* g3    = (const float*)d_in[8];
    const float* b3    = (const float*)d_in[9];
    const float* w4    = (const float*)d_in[10];
    const float* g4    = (const float*)d_in[11];
    const float* b4    = (const float*)d_in[12];
    const float* w5    = (const float*)d_in[13];
    const float* g5    = (const float*)d_in[14];
    const float* b5    = (const float*)d_in[15];
    const float* wemb  = (const float*)d_in[16];
    const float* wclu  = (const float*)d_in[17];
    float* out = (float*)d_out;

    static float* p_xt = nullptr;
    static float* p_xcat = nullptr;
    if (!p_xt) {
        cudaGetSymbolAddress((void**)&p_xt, g_xt);
        cudaGetSymbolAddress((void**)&p_xcat, g_xcat);
        cudaStreamCreateWithFlags(&g_sA, cudaStreamNonBlocking);
        for (int l = 0; l < 4; l++) {
            cudaEventCreateWithFlags(&g_evF[l], cudaEventDisableTiming);
            cudaEventCreateWithFlags(&g_evK[l], cudaEventDisableTiming);
        }
    }

    xt_kernel<<<BB * NN / 256, 256>>>(x);

    run_block(0, p_xt,              3 * NN,   3,   w1, g1, b1,  64, 0);
    run_block(1, p_xcat,            512 * NN, 64,  w2, g2, b2,  64, 64);
    run_block(2, p_xcat + 64 * NN,  512 * NN, 64,  w3, g3, b3, 128, 128);
    run_block(3, p_xcat + 128 * NN, 512 * NN, 128, w4, g4, b4, 256, 256);

    init5_kernel<<<(BB * 512 + 255) / 256, 256>>>();
    dim3 gg5(NN / 128, 512 / 128, BB);
    gemm5_kernel<<<gg5, 256>>>(w5);
    finalize_bn<<<2, 256>>>(g5, b5, 1.0f / (float)(BB * NN), 512);
    pool5<<<(BB * 512 + 255) / 256, 256>>>(out);
    final_kernel<<<1, 256>>>(wemb, wclu, out);
}

// round 17
// speedup vs baseline: 1.0225x; 1.0121x over previous
#include <cuda_runtime.h>
#include <cstdint>

#define BB 8
#define NN 2048
#define KK 20
#define TPW 4    // rows (warps) per topk block
#define NT (NN / 128)            // 16 tiles per dim
#define NPAIR (NT * (NT + 1) / 2) // 136 upper-tri tile pairs
#define CLCAP 512                 // compacted candidate-list capacity per warp

// ---------------- static scratch (no runtime allocation allowed) ----------------
__device__ float g_xt[BB * 3 * NN];
__device__ float g_xx[BB * NN];
__device__ float g_dist[(size_t)BB * NN * NN];          // 134 MB (also reused as vmax/vmin scratch)
__device__ int   g_idx[BB * NN * KK];
__device__ float g_A[(size_t)BB * 256 * NN];            // [b][o][n] 16 MB
__device__ float g_Cc[(size_t)BB * 256 * NN];           // [b][o][n] 16 MB
__device__ float g_xcat[(size_t)BB * 512 * NN];         // [b][c][n] 33 MB (x1|x2|x3|x4)
__device__ float g_y5[(size_t)BB * 512 * NN];           // 33 MB partial-acc buffer for gemm5 split
__device__ float g_sum[512];
__device__ float g_sumsq[512];
__device__ float g_scale[512];
__device__ float g_shift[512];
__device__ float g_pooled[BB * 512];
__device__ unsigned g_ymax[BB * 512];
__device__ unsigned g_ymin[BB * 512];

// ---------------- transpose x (B,N,3) -> (B,3,N) ----------------
__global__ void xt_kernel(const float* __restrict__ x) {
    int i = blockIdx.x * 256 + threadIdx.x;       // b*NN + n
    if (i >= BB * NN) return;
    int b = i >> 11, n = i & (NN - 1);
    #pragma unroll
    for (int c = 0; c < 3; c++)
        g_xt[(b * 3 + c) * NN + n] = x[(size_t)i * 3 + c];
}

// ---------------- squared norms per point ----------------
__global__ void xx_kernel(const float* __restrict__ Xall, int C, int bstride) {
    int i = blockIdx.x * 256 + threadIdx.x;       // b*NN + n
    int b = i >> 11, n = i & (NN - 1);
    const float* X = Xall + (size_t)b * bstride + n;
    float s = 0.f;
    for (int c = 0; c < C; c++) { float v = X[(size_t)c * NN]; s += v * v; }
    g_xx[i] = s;
}

// ---------------- distance matrix: SYMMETRIC upper-tri tile pairs (R12-exact) ----------------
__global__ __launch_bounds__(256) void knn_dist_kernel(const float* __restrict__ Xall,
                                                       int C, int bstride) {
    int b = blockIdx.z;
    const float* X = Xall + (size_t)b * bstride;
    const float* xxr = g_xx + b * NN;
    float* D = g_dist + (size_t)b * NN * NN;

    // decode upper-tri pair (ti <= tj)
    int pair = blockIdx.x;
    int ti = 0, remp = pair;
    while (remp >= NT - ti) { remp -= NT - ti; ti++; }
    int tj = ti + remp;
    int n0 = ti * 128, m0 = tj * 128;

    __shared__ float Ns[2][8][132];
    __shared__ float Ms[2][8][132];
    __shared__ float Ts[32][132];                  // slab transpose buffer
    int t = threadIdx.x;
    int to = t >> 4, tn = t & 15;
    int lk = (t * 4) >> 7, lc = (t * 4) & 127;     // this thread's load slot
    float acc[8][8] = {};
    int nch = (C + 7) / 8;

    // preload chunk 0
    {
        float4 vn = make_float4(0.f, 0.f, 0.f, 0.f), vm = vn;
        if (lk < C) {
            vn = *reinterpret_cast<const float4*>(&X[(size_t)lk * NN + n0 + lc]);
            vm = *reinterpret_cast<const float4*>(&X[(size_t)lk * NN + m0 + lc]);
        }
        *reinterpret_cast<float4*>(&Ns[0][lk][lc]) = vn;
        *reinterpret_cast<float4*>(&Ms[0][lk][lc]) = vm;
    }
    __syncthreads();

    for (int ch = 0; ch < nch; ch++) {
        int cur = ch & 1;
        float4 pn = make_float4(0.f, 0.f, 0.f, 0.f), pm = pn;
        if (ch + 1 < nch) {
            int kg = (ch + 1) * 8 + lk;
            if (kg < C) {
                pn = *reinterpret_cast<const float4*>(&X[(size_t)kg * NN + n0 + lc]);
                pm = *reinterpret_cast<const float4*>(&X[(size_t)kg * NN + m0 + lc]);
            }
        }
        #pragma unroll
        for (int k = 0; k < 8; k++) {
            float a[8], bb_[8];
            *reinterpret_cast<float4*>(&a[0]) = *reinterpret_cast<const float4*>(&Ns[cur][k][to * 8]);
            *reinterpret_cast<float4*>(&a[4]) = *reinterpret_cast<const float4*>(&Ns[cur][k][to * 8 + 4]);
            *reinterpret_cast<float4*>(&bb_[0]) = *reinterpret_cast<const float4*>(&Ms[cur][k][tn * 8]);
            *reinterpret_cast<float4*>(&bb_[4]) = *reinterpret_cast<const float4*>(&Ms[cur][k][tn * 8 + 4]);
            #pragma unroll
            for (int i = 0; i < 8; i++)
                #pragma unroll
                for (int j = 0; j < 8; j++)
                    acc[i][j] += a[i] * bb_[j];
        }
        __syncthreads();
        if (ch + 1 < nch) {
            *reinterpret_cast<float4*>(&Ns[cur ^ 1][lk][lc]) = pn;
            *reinterpret_cast<float4*>(&Ms[cur ^ 1][lk][lc]) = pm;
            __syncthreads();
        }
    }

    // direct tile write (rows n, cols m)
    #pragma unroll
    for (int i = 0; i < 8; i++) {
        int n = n0 + to * 8 + i;
        float xn = xxr[n];
        #pragma unroll
        for (int jj = 0; jj < 2; jj++) {
            float4 v4;
            float* vp = &v4.x;
            #pragma unroll
            for (int j = 0; j < 4; j++) {
                int m = m0 + tn * 8 + jj * 4 + j;
                float v = 2.0f * acc[i][jj * 4 + j] - xn;  // diag: 2v - v = v exactly
                vp[j] = v - xxr[m];                        // diag: v - v = 0 exactly
            }
            *reinterpret_cast<float4*>(&D[(size_t)n * NN + m0 + tn * 8 + jj * 4]) = v4;
        }
    }

    // mirrored tile write (rows m, cols n) via 32-row slab transpose in smem
    if (ti != tj) {
        #pragma unroll
        for (int p = 0; p < 4; p++) {
            __syncthreads();                       // protect Ts from previous slab reads
            if ((tn >> 2) == p) {
                int lt = tn & 3;
                #pragma unroll
                for (int j = 0; j < 8; j++) {
                    int m = m0 + tn * 8 + j;
                    float xm = xxr[m];
                    #pragma unroll
                    for (int i = 0; i < 8; i++) {
                        int n = n0 + to * 8 + i;
                        float v = 2.0f * acc[i][j] - xm;   // mirror: xx[m] first
                        Ts[lt * 8 + j][to * 8 + i] = v - xxr[n];
                    }
                }
            }
            __syncthreads();
            int lm = t >> 3;                        // 0..31
            int c0 = (t & 7) * 16;
            int mg = m0 + p * 32 + lm;
            float* drow = &D[(size_t)mg * NN + n0 + c0];
            #pragma unroll
            for (int q = 0; q < 4; q++)
                *reinterpret_cast<float4*>(&drow[q * 4]) =
                    *reinterpret_cast<const float4*>(&Ts[lm][c0 + q * 4]);
        }
    }
}

// ---------------- top-K: warp-per-row radix select; pass-0 candidate compaction (R16) -------
__global__ __launch_bounds__(32 * TPW) void topk_kernel() {
    __shared__ unsigned hist[TPW][256];
    __shared__ int cand[TPW][64];
    __shared__ unsigned skey[TPW][32][32];   // [warp][r-32][lane], 16 KB, conflict-free
    __shared__ unsigned cl[TPW][CLCAP];      // compacted candidate keys, 8 KB
    int warp = threadIdx.x >> 5, lane = threadIdx.x & 31;
    int row = blockIdx.x * TPW + warp;       // b*NN + n
    const float4* D4 = reinterpret_cast<const float4*>(g_dist + (size_t)row * NN);
    unsigned lmask_lt = (1u << lane) - 1u;

    unsigned key[32];
    #pragma unroll
    for (int j = 0; j < 16; j++) {
        float4 d4 = D4[j * 32 + lane];
        const float* dp = &d4.x;
        #pragma unroll
        for (int q = 0; q < 4; q++) {
            unsigned u = __float_as_uint(dp[q]);
            unsigned k = (u & 0x80000000u) ? ~u : (u | 0x80000000u);
            if (j < 8) key[j * 4 + q] = k;
            else       skey[warp][(j - 8) * 4 + q][lane] = k;
        }
    }
    __syncwarp();

    unsigned prefix = 0; int rem = KK;
    int lcnt = 0; bool compacted = false;
    #pragma unroll
    for (int pass = 0; pass < 4; pass++) {
        int shift = 24 - 8 * pass;
        #pragma unroll
        for (int j = lane; j < 256; j += 32) hist[warp][j] = 0;
        __syncwarp();
        if (pass == 0) {
            #pragma unroll
            for (int r = 0; r < 32; r++)
                atomicAdd(&hist[warp][key[r] >> 24], 1u);
            #pragma unroll
            for (int r = 32; r < 64; r++)
                atomicAdd(&hist[warp][skey[warp][r - 32][lane] >> 24], 1u);
        } else if (compacted) {
            for (int idx = lane; idx < lcnt; idx += 32) {
                unsigned k = cl[warp][idx];
                if ((k >> (shift + 8)) == prefix)
                    atomicAdd(&hist[warp][(k >> shift) & 0xFF], 1u);
            }
        } else {
            #pragma unroll
            for (int r = 0; r < 32; r++) {
                unsigned k = key[r];
                if ((k >> (shift + 8)) == prefix)
                    atomicAdd(&hist[warp][(k >> shift) & 0xFF], 1u);
            }
            #pragma unroll
            for (int r = 32; r < 64; r++) {
                unsigned k = skey[warp][r - 32][lane];
                if ((k >> (shift + 8)) == prefix)
                    atomicAdd(&hist[warp][(k >> shift) & 0xFF], 1u);
            }
        }
        __syncwarp();
        int base = 255 - lane * 8;
        unsigned h[8]; unsigned s = 0;
        #pragma unroll
        for (int j = 0; j < 8; j++) { h[j] = hist[warp][base - j]; s += h[j]; }
        unsigned pre = s;
        #pragma unroll
        for (int off = 1; off < 32; off <<= 1) {
            unsigned v = __shfl_up_sync(0xffffffffu, pre, off);
            if (lane >= off) pre += v;
        }
        unsigned excl = pre - s;
        bool owner = (excl < (unsigned)rem) && ((unsigned)rem <= excl + s);
        unsigned m = __ballot_sync(0xffffffffu, owner);
        int ol = __ffs(m) - 1;
        unsigned nb = 0; int nrem = 0; int ncnt = 0;
        if (owner) {
            unsigned cum = excl;
            #pragma unroll
            for (int j = 0; j < 8; j++) {
                if (cum + h[j] >= (unsigned)rem) {
                    nb = (unsigned)(base - j); nrem = rem - (int)cum; ncnt = (int)h[j]; break;
                }
                cum += h[j];
            }
        }
        nb = __shfl_sync(0xffffffffu, nb, ol);
        nrem = __shfl_sync(0xffffffffu, nrem, ol);
        ncnt = __shfl_sync(0xffffffffu, ncnt, ol);
        prefix = (prefix << 8) | nb;
        rem = nrem;
        __syncwarp();

        if (pass == 0 && ncnt <= CLCAP) {
            int cbase = 0;
            #pragma unroll
            for (int r = 0; r < 64; r++) {
                unsigned k = (r < 32) ? key[r] : skey[warp][r - 32][lane];
                bool match = ((k >> 24) == prefix);
                unsigned mm = __ballot_sync(0xffffffffu, match);
                if (match) cl[warp][cbase + __popc(mm & lmask_lt)] = k;
                cbase += __popc(mm);
            }
            lcnt = ncnt;
            compacted = true;
            __syncwarp();
        }
    }

    unsigned T = prefix;                 // key of the 20th largest
    int* outp = &g_idx[(size_t)row * KK];
    int baseG = 0, baseC = 0;
    #pragma unroll
    for (int r = 0; r < 64; r++) {
        unsigned k = (r < 32) ? key[r] : skey[warp][r - 32][lane];
        bool g = (k > T), e = (k == T);
        unsigned mg = __ballot_sync(0xffffffffu, g);
        unsigned me = __ballot_sync(0xffffffffu, e);
        int i = (r >> 2) * 128 + lane * 4 + (r & 3);
        if (g) outp[baseG + __popc(mg & lmask_lt)] = i;
        if (e) {
            int c = baseC + __popc(me & lmask_lt);
            if (c < 64) cand[warp][c] = i;
        }
        baseG += __popc(mg);
        baseC += __popc(me);
    }
    __syncwarp();
    if (lane == 0) {
        int base = baseG;
        int cc = baseC;
        if (cc == rem) {
            for (int i = 0; i < rem; i++) outp[base + i] = cand[warp][i];
        } else if (cc <= 64) {
            for (int r = 0; r < rem; r++) {          // ties: lowest indices
                int best = NN, bi = -1;
                for (int i = 0; i < cc; i++)
                    if (cand[warp][i] < best) { best = cand[warp][i]; bi = i; }
                outp[base + r] = best;
                cand[warp][bi] = NN;
            }
        } else {                                     // pathological: many exact ties
            const float* D = g_dist + (size_t)row * NN;
            int got = 0;
            for (int i = 0; i < NN && got < rem; i++) {
                unsigned u = __float_as_uint(D[i]);
                unsigned k = (u & 0x80000000u) ? ~u : (u | 0x80000000u);
                if (k == T) outp[base + got++] = i;
            }
        }
    }
}

// ---------------- edge GEMM: A[o][n] = Wl@X, Cc[o][n] = (Wr-Wl)@X  (R9-exact) ----------------
__global__ __launch_bounds__(256) void edge_gemm_kernel(const float* __restrict__ W,
                                                        const float* __restrict__ Xall,
                                                        int C, int O, int bstride) {
    int b = blockIdx.z;
    const float* X = Xall + (size_t)b * bstride;
    float* Aout = g_A + (size_t)b * O * NN;
    float* Cout = g_Cc + (size_t)b * O * NN;
    int o0 = blockIdx.y * 64, n0 = blockIdx.x * 64;
    __shared__ float Xs[16][68];
    __shared__ float Wl[16][68];
    __shared__ float Wd[16][68];
    int t = threadIdx.x;
    int to = t >> 4, tn = t & 15;
    float accA[4][4] = {}, accC[4][4] = {};
    int C2 = 2 * C;
    for (int kk = 0; kk < C; kk += 16) {
        for (int i = t; i < 16 * 64; i += 256) {
            int k = i & 15, o = i >> 4;
            float wl = 0.f, wr = 0.f;
            if (kk + k < C) {
                wl = W[(size_t)(o0 + o) * C2 + kk + k];
                wr = W[(size_t)(o0 + o) * C2 + C + kk + k];
            }
            Wl[k][o] = wl; Wd[k][o] = wr - wl;
        }
        for (int i = t; i < 16 * 64; i += 256) {
            int k = i >> 6, n = i & 63;
            Xs[k][n] = (kk + k < C) ? X[(size_t)(kk + k) * NN + n0 + n] : 0.f;
        }
        __syncthreads();
        #pragma unroll
        for (int k = 0; k < 16; k++) {
            float4 wo4 = *reinterpret_cast<const float4*>(&Wl[k][to * 4]);
            float4 wd4 = *reinterpret_cast<const float4*>(&Wd[k][to * 4]);
            float4 xv4 = *reinterpret_cast<const float4*>(&Xs[k][tn * 4]);
            const float* wo = &wo4.x;
            const float* wd = &wd4.x;
            const float* xv = &xv4.x;
            #pragma unroll
            for (int i = 0; i < 4; i++)
                #pragma unroll
                for (int j = 0; j < 4; j++) {
                    accA[i][j] += wo[i] * xv[j];
                    accC[i][j] += wd[i] * xv[j];
                }
        }
        __syncthreads();
    }
    #pragma unroll
    for (int i = 0; i < 4; i++) {
        int o = o0 + to * 4 + i;
        float4 a4, c4;
        #pragma unroll
        for (int j = 0; j < 4; j++) { (&a4.x)[j] = accA[i][j]; (&c4.x)[j] = accC[i][j]; }
        *reinterpret_cast<float4*>(&Aout[(size_t)o * NN + n0 + tn * 4]) = a4;
        *reinterpret_cast<float4*>(&Cout[(size_t)o * NN + n0 + tn * 4]) = c4;
    }
}

// ---------------- gemm5 split over K: PHASE 0 = K[0,256) store acc; PHASE 1 = resume + stats
// The fp32 FMA chain continues bit-exactly across the gmem round trip of acc.
template<int PHASE>
__global__ __launch_bounds__(256) void gemm5_kernel(const float* __restrict__ W) {
    int b = blockIdx.z;
    const float* X = g_xcat + (size_t)b * 512 * NN;
    float* Y = g_y5 + (size_t)b * 512 * NN;
    int o0 = blockIdx.y * 128, n0 = blockIdx.x * 128;
    __shared__ float Xs[2][8][132];
    __shared__ float Ws[2][8][132];
    int t = threadIdx.x;
    int to = t >> 4, tn = t & 15;
    int lo = t & 127, lhalf = (t >> 7) * 4;
    int lk = (t * 4) >> 7, ln = (t * 4) & 127;
    const int CH0 = (PHASE == 0) ? 0 : 32;
    const int CH1 = (PHASE == 0) ? 32 : 64;
    float acc[8][8];
    if (PHASE == 0) {
        #pragma unroll
        for (int i = 0; i < 8; i++)
            #pragma unroll
            for (int j = 0; j < 8; j++) acc[i][j] = 0.f;
    } else {
        #pragma unroll
        for (int i = 0; i < 8; i++) {
            int o = o0 + to * 8 + i;
            #pragma unroll
            for (int jj = 0; jj < 2; jj++) {
                float4 a4 = *reinterpret_cast<const float4*>(&Y[(size_t)o * NN + n0 + tn * 8 + jj * 4]);
                #pragma unroll
                for (int j = 0; j < 4; j++) acc[i][jj * 4 + j] = (&a4.x)[j];
            }
        }
    }

    // preload first chunk
    {
        int kk = CH0 * 8;
        float4 w4 = *reinterpret_cast<const float4*>(&W[(size_t)(o0 + lo) * 512 + kk + lhalf]);
        const float* wp = &w4.x;
        #pragma unroll
        for (int q = 0; q < 4; q++) Ws[0][lhalf + q][lo] = wp[q];
        *reinterpret_cast<float4*>(&Xs[0][lk][ln]) =
            *reinterpret_cast<const float4*>(&X[(size_t)(kk + lk) * NN + n0 + ln]);
    }
    __syncthreads();

    for (int ch = CH0; ch < CH1; ch++) {
        int cur = (ch - CH0) & 1;
        float4 pw = make_float4(0.f, 0.f, 0.f, 0.f), px = pw;
        if (ch + 1 < CH1) {
            int kk = (ch + 1) * 8;
            pw = *reinterpret_cast<const float4*>(&W[(size_t)(o0 + lo) * 512 + kk + lhalf]);
            px = *reinterpret_cast<const float4*>(&X[(size_t)(kk + lk) * NN + n0 + ln]);
        }
        #pragma unroll
        for (int k = 0; k < 8; k++) {
            float a[8], x_[8];
            *reinterpret_cast<float4*>(&a[0]) = *reinterpret_cast<const float4*>(&Ws[cur][k][to * 8]);
            *reinterpret_cast<float4*>(&a[4]) = *reinterpret_cast<const float4*>(&Ws[cur][k][to * 8 + 4]);
            *reinterpret_cast<float4*>(&x_[0]) = *reinterpret_cast<const float4*>(&Xs[cur][k][tn * 8]);
            *reinterpret_cast<float4*>(&x_[4]) = *reinterpret_cast<const float4*>(&Xs[cur][k][tn * 8 + 4]);
            #pragma unroll
            for (int i = 0; i < 8; i++)
                #pragma unroll
                for (int j = 0; j < 8; j++)
                    acc[i][j] += a[i] * x_[j];
        }
        __syncthreads();
        if (ch + 1 < CH1) {
            const float* wp = &pw.x;
            #pragma unroll
            for (int q = 0; q < 4; q++) Ws[cur ^ 1][lhalf + q][lo] = wp[q];
            *reinterpret_cast<float4*>(&Xs[cur ^ 1][lk][ln]) = px;
            __syncthreads();
        }
    }

    if (PHASE == 0) {
        #pragma unroll
        for (int i = 0; i < 8; i++) {
            int o = o0 + to * 8 + i;
            #pragma unroll
            for (int jj = 0; jj < 2; jj++) {
                float4 a4;
                #pragma unroll
                for (int j = 0; j < 4; j++) (&a4.x)[j] = acc[i][jj * 4 + j];
                *reinterpret_cast<float4*>(&Y[(size_t)o * NN + n0 + tn * 8 + jj * 4]) = a4;
            }
        }
    } else {
        // stats epilogue (R16-exact)
        int b512 = b * 512;
        #pragma unroll
        for (int i = 0; i < 8; i++) {
            int o = o0 + to * 8 + i;
            float s = 0.f, s2 = 0.f, mx = -3.4e38f, mn = 3.4e38f;
            #pragma unroll
            for (int j = 0; j < 8; j++) {
                float v = acc[i][j];
                s += v; s2 += v * v;
                mx = fmaxf(mx, v); mn = fminf(mn, v);
            }
            #pragma unroll
            for (int off = 8; off > 0; off >>= 1) {
                s  += __shfl_down_sync(0xffffffffu, s, off, 16);
                s2 += __shfl_down_sync(0xffffffffu, s2, off, 16);
                mx = fmaxf(mx, __shfl_down_sync(0xffffffffu, mx, off, 16));
                mn = fminf(mn, __shfl_down_sync(0xffffffffu, mn, off, 16));
            }
            if (tn == 0) {
                atomicAdd(&g_sum[o], s);
                atomicAdd(&g_sumsq[o], s2);
                unsigned umx = __float_as_uint(mx);
                umx = (umx & 0x80000000u) ? ~umx : (umx | 0x80000000u);
                atomicMax(&g_ymax[b512 + o], umx);
                unsigned umn = __float_as_uint(mn);
                umn = (umn & 0x80000000u) ? ~umn : (umn | 0x80000000u);
                atomicMin(&g_ymin[b512 + o], umn);
            }
        }
    }
}

// ---------------- zero BN accumulators (edge layers) ----------------
__global__ void zero_stats() {
    int t = blockIdx.x * 256 + threadIdx.x;
    if (t < 512) { g_sum[t] = 0.f; g_sumsq[t] = 0.f; }
}

// ---------------- init for gemm5 stage: sums + ymax/ymin ----------------
__global__ void init5_kernel() {
    int t = blockIdx.x * 256 + threadIdx.x;
    if (t < 512) { g_sum[t] = 0.f; g_sumsq[t] = 0.f; }
    if (t < BB * 512) { g_ymax[t] = 0u; g_ymin[t] = 0xFFFFFFFFu; }
}

// ---------------- BN stats edge: 1024-thread blocks, A row staged 2x (R13-exact) ------------
__global__ __launch_bounds__(1024) void stats_edge(int O) {
    __shared__ float sA[NN];                 // 8 KB: the A[b][o][*] row
    __shared__ float ss[1024], ss2[1024];
    int b = blockIdx.z, o = blockIdx.y;
    int tid = threadIdx.x;
    int n = blockIdx.x * 1024 + tid;
    size_t rowoff = ((size_t)b * O + o) * NN;
    const float* __restrict__ Arow = g_A + rowoff;
    if (tid < NN / 4)
        reinterpret_cast<float4*>(sA)[tid] = reinterpret_cast<const float4*>(Arow)[tid];
    float cv = g_Cc[rowoff + n];
    const int* __restrict__ ip = g_idx + ((size_t)b * NN + n) * KK;
    int idx[KK];
    #pragma unroll
    for (int k = 0; k < KK; k++) idx[k] = ip[k];
    __syncthreads();
    float s = 0.f, s2 = 0.f, mx = -3.4e38f, mn = 3.4e38f;
    #pragma unroll
    for (int k = 0; k < KK; k++) {
        float v = sA[idx[k]] + cv;
        s += v; s2 += v * v;
        mx = fmaxf(mx, v); mn = fminf(mn, v);
    }
    float* vmax = g_dist;
    float* vmin = g_dist + (size_t)BB * 256 * NN;
    vmax[rowoff + n] = mx;
    vmin[rowoff + n] = mn;
    ss[tid] = s; ss2[tid] = s2;
    __syncthreads();
    for (int st = 512; st > 0; st >>= 1) {
        if (tid < st) {
            ss[tid] += ss[tid + st];
            ss2[tid] += ss2[tid + st];
        }
        __syncthreads();
    }
    if (tid == 0) { atomicAdd(&g_sum[o], ss[0]); atomicAdd(&g_sumsq[o], ss2[0]); }
}

// ---------------- finalize BN scale/shift ----------------
__global__ void finalize_bn(const float* __restrict__ gam, const float* __restrict__ bet,
                            float inv_cnt, int O) {
    int o = blockIdx.x * 256 + threadIdx.x;
    if (o >= O) return;
    float mean = g_sum[o] * inv_cnt;
    float var = g_sumsq[o] * inv_cnt - mean * mean;
    float sc = gam[o] * rsqrtf(var + 1e-5f);
    g_scale[o] = sc;
    g_shift[o] = bet[o] - mean * sc;
}

// ---------------- BN apply + leakyReLU + max over k (vectorized; per-element math R9-exact) -
__global__ __launch_bounds__(256) void apply_edge(int O, int coff) {
    int i4 = blockIdx.x * 256 + threadIdx.x;      // index of a float4 group
    int n = (i4 * 4) & (NN - 1);
    int bo = (i4 * 4) >> 11;
    int o = bo % O, b = bo / O;
    float sc = g_scale[o], sh = g_shift[o];
    const float* vmax = g_dist;
    const float* vmin = g_dist + (size_t)BB * 256 * NN;
    const float* src = (sc >= 0.f) ? vmax : vmin;
    float4 v4 = *reinterpret_cast<const float4*>(&src[(size_t)i4 * 4]);
    float* vp = &v4.x;
    #pragma unroll
    for (int j = 0; j < 4; j++) {
        float v = vp[j] * sc + sh;
        vp[j] = (v > 0.f) ? v : 0.2f * v;
    }
    *reinterpret_cast<float4*>(&g_xcat[((size_t)b * 512 + coff + o) * NN + n]) = v4;
}

// ---------------- pool5: decode per-(b,o) max/min key, BN apply + lrelu -> pooled/feat ------
__global__ void pool5(float* __restrict__ out) {
    int i = blockIdx.x * 256 + threadIdx.x;       // b*512 + o
    if (i >= BB * 512) return;
    int o = i & 511;
    float sc = g_scale[o], sh = g_shift[o];
    unsigned k = (sc >= 0.f) ? g_ymax[i] : g_ymin[i];
    unsigned u = (k & 0x80000000u) ? (k & 0x7FFFFFFFu) : ~k;
    float v = __uint_as_float(u);
    v = v * sc + sh;
    v = (v > 0.f) ? v : 0.2f * v;
    g_pooled[i] = v;
    out[i] = v;                                   // feat (B,1,512)
}

// ---------------- embedding + clustering ----------------
__global__ __launch_bounds__(256) void final_kernel(const float* __restrict__ w_emb,
                                                    const float* __restrict__ w_clu,
                                                    float* __restrict__ out) {
    __shared__ float sp[BB * 512];
    __shared__ float se[BB * 128];
    __shared__ float sq[BB * 10];
    __shared__ float ssum[BB];
    int t = threadIdx.x;
    for (int i = t; i < BB * 512; i += 256) sp[i] = g_pooled[i];
    __syncthreads();
    for (int i = t; i < BB * 128; i += 256) {
        int b = i >> 7, f = i & 127;
        float s = 0.f;
        for (int o = 0; o < 512; o++) s += sp[b * 512 + o] * w_emb[(size_t)f * 512 + o];
        se[i] = s;
        out[BB * 512 + i] = s;                    // embedding (B,128)
    }
    __syncthreads();
    if (t < 80) {
        int b = t / 10, c = t % 10;
        float d2 = 0.f;
        for (int f = 0; f < 128; f++) {
            float dd = se[b * 128 + f] - w_clu[c * 128 + f];
            d2 += dd * dd;
        }
        sq[t] = 1.0f / (1.0f + d2);               // alpha=1 -> power -1
    }
    __syncthreads();
    if (t < 8) {
        float s = 0.f;
        for (int c = 0; c < 10; c++) s += sq[t * 10 + c];
        ssum[t] = s;
    }
    __syncthreads();
    if (t < 80) out[BB * 512 + BB * 128 + t] = sq[t] / ssum[t / 10];
}

// ---------------- host launch ----------------
static cudaStream_t g_sA = nullptr, g_sC = nullptr;
static cudaEvent_t g_evF[4], g_evK[4];
static cudaEvent_t g_evL3, g_evP;

static void run_block(int layer, const float* Xsrc, int bstride, int Cin,
                      const float* W, const float* gam, const float* bet,
                      int O, int coff) {
    // fork: KNN chain (xx -> dist -> topk) on stream A; edge_gemm + zero_stats on default
    cudaEventRecord(g_evF[layer], 0);
    cudaStreamWaitEvent(g_sA, g_evF[layer], 0);
    xx_kernel<<<BB * NN / 256, 256, 0, g_sA>>>(Xsrc, Cin, bstride);
    dim3 dg(NPAIR, 1, BB);
    knn_dist_kernel<<<dg, 256, 0, g_sA>>>(Xsrc, Cin, bstride);
    topk_kernel<<<BB * NN / TPW, 32 * TPW, 0, g_sA>>>();
    cudaEventRecord(g_evK[layer], g_sA);

    dim3 eg(NN / 64, O / 64, BB);
    edge_gemm_kernel<<<eg, 256>>>(W, Xsrc, Cin, O, bstride);
    zero_stats<<<2, 256>>>();

    // join: stats needs both g_idx (stream A) and A/Cc (default)
    cudaStreamWaitEvent(0, g_evK[layer], 0);
    dim3 sg(NN / 1024, O, BB);
    stats_edge<<<sg, 1024>>>(O);
    finalize_bn<<<(O + 255) / 256, 256>>>(gam, bet, 1.0f / (float)(BB * NN * KK), O);
    apply_edge<<<(BB * O * NN / 4) / 256, 256>>>(O, coff);
}

extern "C" void kernel_launch(void* const* d_in, const int* in_sizes, int n_in,
                              void* d_out, int out_size) {
    const float* x     = (const float*)d_in[0];
    const float* w1    = (const float*)d_in[1];
    const float* g1    = (const float*)d_in[2];
    const float* b1    = (const float*)d_in[3];
    const float* w2    = (const float*)d_in[4];
    const float* g2    = (const float*)d_in[5];
    const float* b2    = (const float*)d_in[6];
    const float* w3    = (const float*)d_in[7];
    const float* g3    = (const float*)d_in[8];
    const float* b3    = (const float*)d_in[9];
    const float* w4    = (const float*)d_in[10];
    const float* g4    = (const float*)d_in[11];
    const float* b4    = (const float*)d_in[12];
    const float* w5    = (const float*)d_in[13];
    const float* g5    = (const float*)d_in[14];
    const float* b5    = (const float*)d_in[15];
    const float* wemb  = (const float*)d_in[16];
    const float* wclu  = (const float*)d_in[17];
    float* out = (float*)d_out;

    static float* p_xt = nullptr;
    static float* p_xcat = nullptr;
    if (!p_xt) {
        cudaGetSymbolAddress((void**)&p_xt, g_xt);
        cudaGetSymbolAddress((void**)&p_xcat, g_xcat);
        cudaStreamCreateWithFlags(&g_sA, cudaStreamNonBlocking);
        cudaStreamCreateWithFlags(&g_sC, cudaStreamNonBlocking);
        for (int l = 0; l < 4; l++) {
            cudaEventCreateWithFlags(&g_evF[l], cudaEventDisableTiming);
            cudaEventCreateWithFlags(&g_evK[l], cudaEventDisableTiming);
        }
        cudaEventCreateWithFlags(&g_evL3, cudaEventDisableTiming);
        cudaEventCreateWithFlags(&g_evP, cudaEventDisableTiming);
    }

    xt_kernel<<<BB * NN / 256, 256>>>(x);

    run_block(0, p_xt,              3 * NN,   3,   w1, g1, b1,  64, 0);
    run_block(1, p_xcat,            512 * NN, 64,  w2, g2, b2,  64, 64);
    run_block(2, p_xcat + 64 * NN,  512 * NN, 64,  w3, g3, b3, 128, 128);

    // gemm5 phase 0 (K 0..255, xcat channels 0..255 final after layer 3) on stream C,
    // overlapping ALL of layer 4
    cudaEventRecord(g_evL3, 0);
    cudaStreamWaitEvent(g_sC, g_evL3, 0);
    dim3 gg5(NN / 128, 512 / 128, BB);
    gemm5_kernel<0><<<gg5, 256, 0, g_sC>>>(w5);
    cudaEventRecord(g_evP, g_sC);

    run_block(3, p_xcat + 128 * NN, 512 * NN, 128, w4, g4, b4, 256, 256);

    init5_kernel<<<(BB * 512 + 255) / 256, 256>>>();
    cudaStreamWaitEvent(0, g_evP, 0);
    gemm5_kernel<1><<<gg5, 256>>>(w5);
    finalize_bn<<<2, 256>>>(g5, b5, 1.0f / (float)(BB * NN), 512);
    pool5<<<(BB * 512 + 255) / 256, 256>>>(out);
    final_kernel<<<1, 256>>>(wemb, wclu, out);
}